// round 7
// baseline (speedup 1.0000x reference)
#include <cuda_runtime.h>
#include <cuda_fp16.h>
#include <cstdint>

#define DIM    256
#define NE     8192
#define NROWS  32768
#define THRESH 0.04f
#define FLAG_CAP NROWS

// ---- device scratch ----
__device__ float  g_c[NE];                 // 0.5*||e_j||^2
__device__ float  g_cp[4][NE];             // norm partials (deterministic combine)
__device__ int    g_idx[NROWS];
__device__ float  g_eT[NE * DIM];          // fp32 transposed codebook (gather)
__device__ __half g_epk[NE * DIM];         // fp16 codebook, pre-swizzled k64 slices
__device__ double g_diff;
__device__ int    g_nflag;
__device__ int    g_flag[FLAG_CAP];
__device__ unsigned long long g_rkey[FLAG_CAP];

__device__ __forceinline__ uint32_t smem_u32(const void* p) {
    uint32_t a;
    asm("{ .reg .u64 t; cvta.to.shared.u64 t, %1; cvt.u32.u64 %0, t; }" : "=r"(a) : "l"(p));
    return a;
}

__device__ __forceinline__ void ldmx4(uint32_t& r0, uint32_t& r1, uint32_t& r2, uint32_t& r3,
                                      uint32_t addr) {
    asm volatile("ldmatrix.sync.aligned.m8n8.x4.shared.b16 {%0,%1,%2,%3}, [%4];"
                 : "=r"(r0), "=r"(r1), "=r"(r2), "=r"(r3) : "r"(addr));
}

__device__ __forceinline__ void mma16816(float& c0, float& c1, float& c2, float& c3,
                                         uint32_t a0, uint32_t a1, uint32_t a2, uint32_t a3,
                                         uint32_t b0, uint32_t b1) {
    asm volatile(
        "mma.sync.aligned.m16n8k16.row.col.f32.f16.f16.f32 "
        "{%0,%1,%2,%3}, {%4,%5,%6,%7}, {%8,%9}, {%0,%1,%2,%3};"
        : "+f"(c0), "+f"(c1), "+f"(c2), "+f"(c3)
        : "r"(a0), "r"(a1), "r"(a2), "r"(a3), "r"(b0), "r"(b1));
}

#define CP_ASYNC16(dst, src) \
    asm volatile("cp.async.cg.shared.global [%0], [%1], 16;" :: "r"(dst), "l"(src))
#define CP_COMMIT() asm volatile("cp.async.commit_group;" ::: "memory")
#define CP_WAIT1()  asm volatile("cp.async.wait_group 1;" ::: "memory")

// ============================================================
// Prep kernels
// ============================================================
__global__ void norms_part_kernel(const float* __restrict__ embed) {
    int j = blockIdx.x * 256 + threadIdx.x;
    int q = blockIdx.y;                    // dim quarter
    float s = 0.f;
    #pragma unroll 8
    for (int d = q * 64; d < q * 64 + 64; ++d) {
        float v = embed[(size_t)d * NE + j];
        s += v * v;
    }
    g_cp[q][j] = s;
}

__global__ void norms_comb_kernel() {
    int j = blockIdx.x * 256 + threadIdx.x;
    if (blockIdx.x == 0 && threadIdx.x == 0) { g_diff = 0.0; g_nflag = 0; }
    g_c[j] = 0.5f * (((g_cp[0][j] + g_cp[1][j]) + g_cp[2][j]) + g_cp[3][j]);
}

__global__ void transpose_kernel(const float* __restrict__ embed) {
    __shared__ float t[32][33];
    int j0 = blockIdx.x * 32;
    int d0 = blockIdx.y * 32;
    int tx = threadIdx.x, ty = threadIdx.y;   // 32 x 8
    #pragma unroll
    for (int i = 0; i < 32; i += 8)
        t[ty + i][tx] = embed[(size_t)(d0 + ty + i) * NE + (j0 + tx)];
    __syncthreads();
    #pragma unroll
    for (int i = 0; i < 32; i += 8)
        g_eT[(size_t)(j0 + ty + i) * DIM + (d0 + tx)] = t[tx][ty + i];
}

// Pack codebook into fp16, pre-swizzled k64 slices:
// slice (jt, s): codes [jt*128, +128), dims [s*64, +64)
// layout: halves[(jt*4+s)*8192 + n*64 + swg*8 + (k&7)], swg = ((k>>3)^n)&7
__global__ void pack_kernel(const float* __restrict__ embed) {
    int idx = blockIdx.x * 256 + threadIdx.x;    // over DIM*NE
    int d = idx >> 13;           // / NE
    int j = idx & (NE - 1);
    float v = embed[idx];
    int jt = j >> 7, n = j & 127;
    int s = d >> 6, k = d & 63;
    int swg = ((k >> 3) ^ n) & 7;
    size_t dst = ((size_t)(jt * 4 + s) << 13) + (size_t)n * 64 + swg * 8 + (k & 7);
    g_epk[dst] = __float2half(v);
}

// ============================================================
// Main HMMA kernel: 128 threads (4 warps), 64 rows per CTA, 512 CTAs.
// 3 CTAs/SM (launch_bounds cap). A register-resident; B cp.async 3-stage.
// ============================================================
__global__ void __launch_bounds__(128, 3)
tc_argmin_kernel(const float* __restrict__ input) {
    __shared__ __align__(16) __half eB[3][8192];  // 3 x 16KB swizzled slices = 48KB

    const int tid  = threadIdx.x;
    const int wid  = tid >> 5;
    const int lane = tid & 31;
    const int row0 = blockIdx.x * 64;
    const int mat  = lane >> 3;
    const int rr   = lane & 7;

    const uint32_t eb[3] = { smem_u32(&eB[0][0]), smem_u32(&eB[1][0]), smem_u32(&eB[2][0]) };

    // ================= prologue: A fragments (2 rounds x 32 rows) =================
    uint32_t areg[64];   // 16 k16-chunks x 4
    {
        __half* stage = &eB[0][0];
        const int r = tid & 31;     // row within round
        const int p = tid >> 5;     // segment 0..3
        #pragma unroll 1
        for (int round = 0; round < 2; ++round) {
            const float4* src = reinterpret_cast<const float4*>(
                input + (size_t)(row0 + round * 32 + r) * DIM + p * 64);
            #pragma unroll
            for (int u = 0; u < 8; ++u) {
                float4 fa = src[u * 2 + 0];
                float4 fb = src[u * 2 + 1];
                __half2 h0 = __floats2half2_rn(fa.x, fa.y);
                __half2 h1 = __floats2half2_rn(fa.z, fa.w);
                __half2 h2 = __floats2half2_rn(fb.x, fb.y);
                __half2 h3 = __floats2half2_rn(fb.z, fb.w);
                uint4 pk;
                pk.x = *reinterpret_cast<uint32_t*>(&h0);
                pk.y = *reinterpret_cast<uint32_t*>(&h1);
                pk.z = *reinterpret_cast<uint32_t*>(&h2);
                pk.w = *reinterpret_cast<uint32_t*>(&h3);
                int g = p * 8 + u;
                int swg = (g & 24) | ((g ^ r) & 7);
                *reinterpret_cast<uint4*>(
                    reinterpret_cast<char*>(stage) + r * 512 + swg * 16) = pk;
            }
            __syncthreads();
            if ((wid >> 1) == round) {
                const int m = (wid & 1) * 16 + (mat & 1) * 8 + rr;
                #pragma unroll
                for (int c = 0; c < 16; ++c) {
                    int g = c * 2 + (mat >> 1);
                    int swg = (g & 24) | ((g ^ rr) & 7);
                    uint32_t addr = smem_u32(stage) + (uint32_t)(m * 512 + swg * 16);
                    ldmx4(areg[c * 4 + 0], areg[c * 4 + 1],
                          areg[c * 4 + 2], areg[c * 4 + 3], addr);
                }
            }
            __syncthreads();
        }
    }

    // ================= main loop (cp.async 3-stage) =================
    const char* epk = reinterpret_cast<const char*>(g_epk);

    // prime slices 0, 1 (after prologue: eB[0] free again)
    #pragma unroll
    for (int pt = 0; pt < 2; ++pt) {
        const char* src = epk + (size_t)pt * 16384 + tid * 16;
        #pragma unroll
        for (int it = 0; it < 8; ++it)
            CP_ASYNC16(eb[pt] + (uint32_t)(tid * 16 + it * 2048), src + it * 2048);
        CP_COMMIT();
    }

    float creg[64];
    float bb[2] = {-3.0e38f, -3.0e38f};
    float ss[2] = {-3.0e38f, -3.0e38f};
    int   ii[2] = {0, 0};

    const int hi_n = (mat >> 1) * 8 + rr;
    const int gbit = mat & 1;
    int bufc = 0, bufn = 2;   // buf of slice t, buf of slice t+2

    #pragma unroll 1
    for (int t = 0; t < 256; ++t) {
        const uint32_t ebase = eb[bufc];
        const int s = t & 3;

        CP_WAIT1();
        __syncthreads();

        // issue slice t+2 into the buffer freed by slice t-1
        if (t + 2 < 256) {
            const char* src = epk + (size_t)(t + 2) * 16384 + tid * 16;
            #pragma unroll
            for (int it = 0; it < 8; ++it)
                CP_ASYNC16(eb[bufn] + (uint32_t)(tid * 16 + it * 2048), src + it * 2048);
        }
        CP_COMMIT();

        if (s == 0) {
            #pragma unroll
            for (int q = 0; q < 64; ++q) creg[q] = 0.f;
        }

        // compute: 4 k16 chunks x 16 n-tiles (per warp: 16 rows x 128 codes)
        #pragma unroll
        for (int kc = 0; kc < 4; ++kc) {
            const int ai = (s * 4 + kc) * 4;
            const int swg = ((kc * 2 + gbit) ^ rr) & 7;
            #pragma unroll
            for (int p = 0; p < 8; ++p) {
                uint32_t b0, b1, b2, b3;
                uint32_t addr = ebase + (uint32_t)((p * 16 + hi_n) * 128 + swg * 16);
                ldmx4(b0, b1, b2, b3, addr);
                mma16816(creg[(2*p)*4+0], creg[(2*p)*4+1], creg[(2*p)*4+2], creg[(2*p)*4+3],
                         areg[ai+0], areg[ai+1], areg[ai+2], areg[ai+3], b0, b1);
                mma16816(creg[(2*p+1)*4+0], creg[(2*p+1)*4+1], creg[(2*p+1)*4+2], creg[(2*p+1)*4+3],
                         areg[ai+0], areg[ai+1], areg[ai+2], areg[ai+3], b2, b3);
            }
        }

        // tile end: subtract 0.5||e||^2 (L1-resident) + running top-2
        if (s == 3) {
            const int jt = t >> 2;
            const float2* cb = reinterpret_cast<const float2*>(g_c) + jt * 64 + (lane & 3);
            #pragma unroll
            for (int tl = 0; tl < 16; ++tl) {
                float2 c2 = __ldg(cb + tl * 4);
                int n0 = jt * 128 + tl * 8 + (lane & 3) * 2;
                float v;
                v = creg[tl*4+0] - c2.x;
                if (v > bb[0]) { ss[0] = bb[0]; bb[0] = v; ii[0] = n0; }
                else if (v > ss[0]) ss[0] = v;
                v = creg[tl*4+1] - c2.y;
                if (v > bb[0]) { ss[0] = bb[0]; bb[0] = v; ii[0] = n0 + 1; }
                else if (v > ss[0]) ss[0] = v;
                v = creg[tl*4+2] - c2.x;
                if (v > bb[1]) { ss[1] = bb[1]; bb[1] = v; ii[1] = n0; }
                else if (v > ss[1]) ss[1] = v;
                v = creg[tl*4+3] - c2.y;
                if (v > bb[1]) { ss[1] = bb[1]; bb[1] = v; ii[1] = n0 + 1; }
                else if (v > ss[1]) ss[1] = v;
            }
        }

        bufc = (bufc == 2) ? 0 : bufc + 1;
        bufn = (bufn == 2) ? 0 : bufn + 1;
    }

    // ================= reduction: quad merge, write =================
    #pragma unroll
    for (int sl = 0; sl < 2; ++sl) {
        float b = bb[sl], sec = ss[sl]; int i = ii[sl];
        #pragma unroll
        for (int off = 1; off <= 2; off <<= 1) {
            float ob = __shfl_xor_sync(0xffffffffu, b, off);
            float os = __shfl_xor_sync(0xffffffffu, sec, off);
            int   oi = __shfl_xor_sync(0xffffffffu, i, off);
            if (ob > b || (ob == b && oi < i)) {
                sec = fmaxf(b, os); b = ob; i = oi;
            } else {
                sec = fmaxf(sec, ob);
            }
        }
        if ((lane & 3) == 0) {
            int row = row0 + wid * 16 + (lane >> 2) + sl * 8;
            g_idx[row] = i;
            if (b - sec < THRESH) {
                int sidx = atomicAdd(&g_nflag, 1);
                if (sidx < FLAG_CAP) { g_flag[sidx] = row; g_rkey[sidx] = 0ull; }
            }
        }
    }
}

// ============================================================
// Exact fp32 rescue for narrow-margin rows.
// ============================================================
__device__ __forceinline__ unsigned long long score_key(float v, int j) {
    uint32_t u = __float_as_uint(v);
    u = (u & 0x80000000u) ? ~u : (u | 0x80000000u);
    return ((unsigned long long)u << 32) | (uint32_t)(0xFFFFFFFFu ^ (uint32_t)j);
}

__global__ void rescue_kernel(const float* __restrict__ input,
                              const float* __restrict__ embed) {
    __shared__ float xs[16][DIM];
    __shared__ unsigned long long wb[8][16];
    int nf = g_nflag; if (nf > FLAG_CAP) nf = FLAG_CAP;
    const int tid = threadIdx.x, wid = tid >> 5, lane = tid & 31;

    for (int base = blockIdx.y * 16; base < nf; base += 16 * 16) {
        int nrows = nf - base; if (nrows > 16) nrows = 16;
        __syncthreads();
        for (int i = tid; i < nrows * DIM; i += 256) {
            int r = i >> 8, d = i & 255;
            xs[r][d] = input[(size_t)g_flag[base + r] * DIM + d];
        }
        __syncthreads();

        int j0 = blockIdx.x * 1024 + tid;     // codes j0 + {0,256,512,768}
        float acc[4][16];
        #pragma unroll
        for (int q = 0; q < 4; ++q)
            #pragma unroll
            for (int r = 0; r < 16; ++r) acc[q][r] = 0.f;

        #pragma unroll 4
        for (int d = 0; d < DIM; ++d) {
            float e0 = embed[(size_t)d * NE + j0];
            float e1 = embed[(size_t)d * NE + j0 + 256];
            float e2 = embed[(size_t)d * NE + j0 + 512];
            float e3 = embed[(size_t)d * NE + j0 + 768];
            #pragma unroll
            for (int r = 0; r < 16; ++r) {
                float x = xs[r][d];
                acc[0][r] += e0 * x;
                acc[1][r] += e1 * x;
                acc[2][r] += e2 * x;
                acc[3][r] += e3 * x;
            }
        }
        float c0 = g_c[j0], c1 = g_c[j0 + 256], c2 = g_c[j0 + 512], c3 = g_c[j0 + 768];

        #pragma unroll 1
        for (int r = 0; r < 16; ++r) {
            float bv = acc[0][r] - c0; int bj = j0;
            float v1 = acc[1][r] - c1; if (v1 > bv) { bv = v1; bj = j0 + 256; }
            float v2 = acc[2][r] - c2; if (v2 > bv) { bv = v2; bj = j0 + 512; }
            float v3 = acc[3][r] - c3; if (v3 > bv) { bv = v3; bj = j0 + 768; }
            unsigned long long key = score_key(bv, bj);
            #pragma unroll
            for (int o = 16; o; o >>= 1) {
                unsigned long long other = __shfl_xor_sync(0xffffffffu, key, o);
                if (other > key) key = other;
            }
            if (lane == 0) wb[wid][r] = key;
        }
        __syncthreads();
        if (tid < nrows) {
            unsigned long long k = wb[0][tid];
            #pragma unroll
            for (int w = 1; w < 8; ++w) if (wb[w][tid] > k) k = wb[w][tid];
            atomicMax(&g_rkey[base + tid], k);
        }
    }
}

__global__ void extract_kernel() {
    int nf = g_nflag; if (nf > FLAG_CAP) nf = FLAG_CAP;
    for (int i = threadIdx.x; i < nf; i += 256) {
        unsigned long long k = g_rkey[i];
        g_idx[g_flag[i]] = (int)(0xFFFFFFFFu ^ (uint32_t)(k & 0xFFFFFFFFull));
    }
}

// ============================================================
// Output: gather, commitment loss, indices.
// ============================================================
__global__ void output_kernel(const float* __restrict__ input,
                              float* __restrict__ out, int write_extra) {
    int row  = blockIdx.x * 8 + (threadIdx.x >> 5);
    int lane = threadIdx.x & 31;
    int j = g_idx[row];
    const float4* x4 = reinterpret_cast<const float4*>(input + (size_t)row * DIM);
    const float4* e4 = reinterpret_cast<const float4*>(g_eT + (size_t)j * DIM);
    float4*       q4 = reinterpret_cast<float4*>(out + (size_t)row * DIM);
    float s = 0.f;
    #pragma unroll
    for (int t = 0; t < 2; ++t) {
        int d4 = lane + t * 32;
        float4 e = e4[d4];
        float4 x = x4[d4];
        q4[d4] = e;
        float a = e.x - x.x, b = e.y - x.y, c = e.z - x.z, d = e.w - x.w;
        s += a * a + b * b + c * c + d * d;
    }
    #pragma unroll
    for (int o = 16; o; o >>= 1) s += __shfl_xor_sync(0xffffffffu, s, o);
    if (lane == 0) {
        atomicAdd(&g_diff, (double)s);
        if (write_extra) out[(size_t)NROWS * DIM + 1 + row] = (float)j;
    }
}

__global__ void finalize_kernel(float* __restrict__ out, int write_extra) {
    if (write_extra)
        out[(size_t)NROWS * DIM] = (float)(g_diff * (1.0 / ((double)NROWS * (double)DIM)));
}

// ============================================================
extern "C" void kernel_launch(void* const* d_in, const int* in_sizes, int n_in,
                              void* d_out, int out_size) {
    const float* input = (const float*)d_in[0];
    const float* embed = (const float*)d_in[1];
    if (in_sizes[0] == NE * DIM && in_sizes[1] == NROWS * DIM) {
        input = (const float*)d_in[1];
        embed = (const float*)d_in[0];
    }
    float* out = (float*)d_out;
    int write_extra = (out_size >= NROWS * DIM + 1 + NROWS) ? 1 : 0;

    norms_part_kernel<<<dim3(NE / 256, 4), 256>>>(embed);
    norms_comb_kernel<<<NE / 256, 256>>>();
    transpose_kernel<<<dim3(NE / 32, DIM / 32), dim3(32, 8)>>>(embed);
    pack_kernel<<<DIM * NE / 256, 256>>>(embed);
    tc_argmin_kernel<<<NROWS / 64, 128>>>(input);
    rescue_kernel<<<dim3(8, 16), 256>>>(input, embed);
    extract_kernel<<<1, 256>>>();
    output_kernel<<<NROWS / 8, 256>>>(input, out, write_extra);
    finalize_kernel<<<1, 1>>>(out, write_extra);
}

// round 8
// speedup vs baseline: 1.2061x; 1.2061x over previous
#include <cuda_runtime.h>
#include <cuda_fp16.h>
#include <cstdint>

#define DIM    256
#define NE     8192
#define NROWS  32768
#define THRESH 0.04f
#define FLAG_CAP NROWS

// ---- device scratch ----
__device__ float  g_c[NE];                 // 0.5*||e_j||^2
__device__ float  g_cp[4][NE];             // norm partials (deterministic combine)
__device__ int    g_idx[NROWS];
__device__ float  g_eT[NE * DIM];          // fp32 transposed codebook (gather)
__device__ __half g_epk[NE * DIM];         // fp16 codebook, pre-swizzled k64 slices
__device__ double g_diff;
__device__ int    g_nflag;
__device__ int    g_flag[FLAG_CAP];
__device__ unsigned long long g_rkey[FLAG_CAP];

__device__ __forceinline__ uint32_t smem_u32(const void* p) {
    uint32_t a;
    asm("{ .reg .u64 t; cvta.to.shared.u64 t, %1; cvt.u32.u64 %0, t; }" : "=r"(a) : "l"(p));
    return a;
}

__device__ __forceinline__ void ldmx4(uint32_t& r0, uint32_t& r1, uint32_t& r2, uint32_t& r3,
                                      uint32_t addr) {
    asm volatile("ldmatrix.sync.aligned.m8n8.x4.shared.b16 {%0,%1,%2,%3}, [%4];"
                 : "=r"(r0), "=r"(r1), "=r"(r2), "=r"(r3) : "r"(addr));
}

__device__ __forceinline__ void mma16816(float& c0, float& c1, float& c2, float& c3,
                                         uint32_t a0, uint32_t a1, uint32_t a2, uint32_t a3,
                                         uint32_t b0, uint32_t b1) {
    asm volatile(
        "mma.sync.aligned.m16n8k16.row.col.f32.f16.f16.f32 "
        "{%0,%1,%2,%3}, {%4,%5,%6,%7}, {%8,%9}, {%0,%1,%2,%3};"
        : "+f"(c0), "+f"(c1), "+f"(c2), "+f"(c3)
        : "r"(a0), "r"(a1), "r"(a2), "r"(a3), "r"(b0), "r"(b1));
}

// ============================================================
// Prep kernels
// ============================================================
__global__ void norms_part_kernel(const float* __restrict__ embed) {
    int j = blockIdx.x * 256 + threadIdx.x;
    int q = blockIdx.y;                    // dim quarter
    float s = 0.f;
    #pragma unroll 8
    for (int d = q * 64; d < q * 64 + 64; ++d) {
        float v = embed[(size_t)d * NE + j];
        s += v * v;
    }
    g_cp[q][j] = s;
}

__global__ void norms_comb_kernel() {
    int j = blockIdx.x * 256 + threadIdx.x;
    if (blockIdx.x == 0 && threadIdx.x == 0) { g_diff = 0.0; g_nflag = 0; }
    g_c[j] = 0.5f * (((g_cp[0][j] + g_cp[1][j]) + g_cp[2][j]) + g_cp[3][j]);
}

__global__ void transpose_kernel(const float* __restrict__ embed) {
    __shared__ float t[32][33];
    int j0 = blockIdx.x * 32;
    int d0 = blockIdx.y * 32;
    int tx = threadIdx.x, ty = threadIdx.y;   // 32 x 8
    #pragma unroll
    for (int i = 0; i < 32; i += 8)
        t[ty + i][tx] = embed[(size_t)(d0 + ty + i) * NE + (j0 + tx)];
    __syncthreads();
    #pragma unroll
    for (int i = 0; i < 32; i += 8)
        g_eT[(size_t)(j0 + ty + i) * DIM + (d0 + tx)] = t[tx][ty + i];
}

// Pack codebook into fp16, pre-swizzled k64 slices:
// slice (jt, s): codes [jt*128, +128), dims [s*64, +64)
// layout: halves[(jt*4+s)*8192 + n*64 + swg*8 + (k&7)], swg = ((k>>3)^n)&7
__global__ void pack_kernel(const float* __restrict__ embed) {
    int idx = blockIdx.x * 256 + threadIdx.x;    // over DIM*NE
    int d = idx >> 13;           // / NE
    int j = idx & (NE - 1);
    float v = embed[idx];
    int jt = j >> 7, n = j & 127;
    int s = d >> 6, k = d & 63;
    int swg = ((k >> 3) ^ n) & 7;
    size_t dst = ((size_t)(jt * 4 + s) << 13) + (size_t)n * 64 + swg * 8 + (k & 7);
    g_epk[dst] = __float2half(v);
}

// ============================================================
// Main HMMA kernel: 256 threads (8 warps), 64 rows x full codebook per CTA.
// Warp tile: m16 x n64, full k resident. 4 m-groups x 2 n-cols.
// 2 CTAs/SM (regs <= 128): 4 warps/SMSP for latency cover.
// B via R5-style register prefetch double buffer.
// ============================================================
__global__ void __launch_bounds__(256, 2)
tc_argmin_kernel(const float* __restrict__ input) {
    __shared__ __align__(16) __half eB[2][8192];  // 2 x 16KB swizzled slices
    __shared__ float sbv[2][64];                  // [ncol][row] best
    __shared__ float ssv[2][64];                  // second
    __shared__ int   sbi[2][64];                  // index

    const int tid  = threadIdx.x;
    const int wid  = tid >> 5;
    const int lane = tid & 31;
    const int mrow = wid >> 1;    // 0..3 : rows mrow*16..+15
    const int ncol = wid & 1;     // 0..1 : codes ncol*64..+63 within slice
    const int row0 = blockIdx.x * 64;
    const int mat  = lane >> 3;
    const int rr   = lane & 7;

    const uint32_t eb0 = smem_u32(&eB[0][0]);
    const uint32_t eb1 = smem_u32(&eB[1][0]);

    // ================= prologue: A fragments =================
    // Stage 32 rows at a time into eB[0] (16KB, swizzled); warp pair loads.
    uint32_t areg[64];   // 16 k16-chunks x 4
    {
        __half* stage = &eB[0][0];
        const int r = tid & 31;     // row within round
        const int p = tid >> 5;     // 32-half segment (0..7)
        #pragma unroll 1
        for (int round = 0; round < 2; ++round) {
            const float4* src = reinterpret_cast<const float4*>(
                input + (size_t)(row0 + round * 32 + r) * DIM + p * 32);
            #pragma unroll
            for (int u = 0; u < 4; ++u) {
                float4 fa = src[u * 2 + 0];
                float4 fb = src[u * 2 + 1];
                __half2 h0 = __floats2half2_rn(fa.x, fa.y);
                __half2 h1 = __floats2half2_rn(fa.z, fa.w);
                __half2 h2 = __floats2half2_rn(fb.x, fb.y);
                __half2 h3 = __floats2half2_rn(fb.z, fb.w);
                uint4 pk;
                pk.x = *reinterpret_cast<uint32_t*>(&h0);
                pk.y = *reinterpret_cast<uint32_t*>(&h1);
                pk.z = *reinterpret_cast<uint32_t*>(&h2);
                pk.w = *reinterpret_cast<uint32_t*>(&h3);
                int g = p * 4 + u;
                int swg = (g & 24) | ((g ^ r) & 7);
                *reinterpret_cast<uint4*>(
                    reinterpret_cast<char*>(stage) + r * 512 + swg * 16) = pk;
            }
            __syncthreads();
            if ((wid >> 2) == round) {       // 4 warps: mrow pair x 2 ncols
                const int m = (mrow & 1) * 16 + (mat & 1) * 8 + rr;
                #pragma unroll
                for (int c = 0; c < 16; ++c) {
                    int g = c * 2 + (mat >> 1);
                    int swg = (g & 24) | ((g ^ rr) & 7);
                    uint32_t addr = smem_u32(stage) + (uint32_t)(m * 512 + swg * 16);
                    ldmx4(areg[c * 4 + 0], areg[c * 4 + 1],
                          areg[c * 4 + 2], areg[c * 4 + 3], addr);
                }
            }
            __syncthreads();
        }
    }

    // ================= main loop (register prefetch, 2-buffer) =================
    const uint4* epk = reinterpret_cast<const uint4*>(g_epk);

    // initial: slice 0 into eB[0]
    {
        uint4 v0 = epk[tid], v1 = epk[tid + 256], v2 = epk[tid + 512], v3 = epk[tid + 768];
        uint4* dst = reinterpret_cast<uint4*>(&eB[0][0]);
        dst[tid] = v0; dst[tid + 256] = v1; dst[tid + 512] = v2; dst[tid + 768] = v3;
    }
    __syncthreads();

    float creg[32];
    float bb[2] = {-3.0e38f, -3.0e38f};
    float ss[2] = {-3.0e38f, -3.0e38f};
    int   ii[2] = {0, 0};

    const int hi_n = (mat >> 1) * 8 + rr;
    const int gbit = mat & 1;

    #pragma unroll 1
    for (int t = 0; t < 256; ++t) {
        const int buf = t & 1;
        const uint32_t ebase = buf ? eb1 : eb0;
        const int s = t & 3;

        // 1) prefetch next slice (LDG into regs; consumed at step 5)
        uint4 v0, v1, v2, v3;
        const bool havenext = (t + 1) < 256;
        if (havenext) {
            const uint4* src = epk + (size_t)(t + 1) * 1024;
            v0 = src[tid]; v1 = src[tid + 256]; v2 = src[tid + 512]; v3 = src[tid + 768];
        }

        // 2) tile start: zero accumulators
        if (s == 0) {
            #pragma unroll
            for (int q = 0; q < 32; ++q) creg[q] = 0.f;
        }

        // 3) compute: 4 k16 chunks x 8 n-tiles (warp: 16 rows x 64 codes)
        #pragma unroll
        for (int kc = 0; kc < 4; ++kc) {
            const int ai = (s * 4 + kc) * 4;
            const int swg = ((kc * 2 + gbit) ^ rr) & 7;
            #pragma unroll
            for (int p = 0; p < 4; ++p) {
                const int P = ncol * 4 + p;          // global n16-pair in slice
                uint32_t b0, b1, b2, b3;
                uint32_t addr = ebase + (uint32_t)((P * 16 + hi_n) * 128 + swg * 16);
                ldmx4(b0, b1, b2, b3, addr);
                mma16816(creg[(2*p)*4+0], creg[(2*p)*4+1], creg[(2*p)*4+2], creg[(2*p)*4+3],
                         areg[ai+0], areg[ai+1], areg[ai+2], areg[ai+3], b0, b1);
                mma16816(creg[(2*p+1)*4+0], creg[(2*p+1)*4+1], creg[(2*p+1)*4+2], creg[(2*p+1)*4+3],
                         areg[ai+0], areg[ai+1], areg[ai+2], areg[ai+3], b2, b3);
            }
        }

        // 4) tile end: subtract 0.5||e||^2 (L1-resident LDG) + running top-2
        if (s == 3) {
            const int jt = t >> 2;
            const float2* cb = reinterpret_cast<const float2*>(g_c)
                             + jt * 64 + ncol * 32 + (lane & 3);
            #pragma unroll
            for (int tl = 0; tl < 8; ++tl) {
                float2 c2 = __ldg(cb + tl * 4);
                int n0 = jt * 128 + ncol * 64 + tl * 8 + (lane & 3) * 2;
                float v;
                v = creg[tl*4+0] - c2.x;
                if (v > bb[0]) { ss[0] = bb[0]; bb[0] = v; ii[0] = n0; }
                else if (v > ss[0]) ss[0] = v;
                v = creg[tl*4+1] - c2.y;
                if (v > bb[0]) { ss[0] = bb[0]; bb[0] = v; ii[0] = n0 + 1; }
                else if (v > ss[0]) ss[0] = v;
                v = creg[tl*4+2] - c2.x;
                if (v > bb[1]) { ss[1] = bb[1]; bb[1] = v; ii[1] = n0; }
                else if (v > ss[1]) ss[1] = v;
                v = creg[tl*4+3] - c2.y;
                if (v > bb[1]) { ss[1] = bb[1]; bb[1] = v; ii[1] = n0 + 1; }
                else if (v > ss[1]) ss[1] = v;
            }
        }

        // 5) store prefetched slice into the other buffer
        if (havenext) {
            uint4* dst = reinterpret_cast<uint4*>(buf ? &eB[0][0] : &eB[1][0]);
            dst[tid] = v0; dst[tid + 256] = v1; dst[tid + 512] = v2; dst[tid + 768] = v3;
        }
        __syncthreads();
    }

    // ================= reduction: quad merge within warp =================
    #pragma unroll
    for (int sl = 0; sl < 2; ++sl) {
        float b = bb[sl], sec = ss[sl]; int i = ii[sl];
        #pragma unroll
        for (int off = 1; off <= 2; off <<= 1) {
            float ob = __shfl_xor_sync(0xffffffffu, b, off);
            float os = __shfl_xor_sync(0xffffffffu, sec, off);
            int   oi = __shfl_xor_sync(0xffffffffu, i, off);
            if (ob > b || (ob == b && oi < i)) {
                sec = fmaxf(b, os); b = ob; i = oi;
            } else {
                sec = fmaxf(sec, ob);
            }
        }
        if ((lane & 3) == 0) {
            int lrow = mrow * 16 + (lane >> 2) + sl * 8;
            sbv[ncol][lrow] = b;
            ssv[ncol][lrow] = sec;
            sbi[ncol][lrow] = i;
        }
    }
    __syncthreads();

    // merge the two n-columns per row; write index; flag narrow margins
    if (tid < 64) {
        float va = sbv[0][tid], vb = sbv[1][tid];
        float sa = ssv[0][tid], sb = ssv[1][tid];
        int   ia = sbi[0][tid], ib = sbi[1][tid];
        float bv, sec; int bi;
        if (va > vb || (va == vb && ia < ib)) { bv = va; bi = ia; sec = fmaxf(vb, sa); }
        else                                   { bv = vb; bi = ib; sec = fmaxf(va, sb); }
        int row = row0 + tid;
        g_idx[row] = bi;
        if (bv - sec < THRESH) {
            int sidx = atomicAdd(&g_nflag, 1);
            if (sidx < FLAG_CAP) { g_flag[sidx] = row; g_rkey[sidx] = 0ull; }
        }
    }
}

// ============================================================
// Exact fp32 rescue for narrow-margin rows.
// ============================================================
__device__ __forceinline__ unsigned long long score_key(float v, int j) {
    uint32_t u = __float_as_uint(v);
    u = (u & 0x80000000u) ? ~u : (u | 0x80000000u);
    return ((unsigned long long)u << 32) | (uint32_t)(0xFFFFFFFFu ^ (uint32_t)j);
}

__global__ void rescue_kernel(const float* __restrict__ input,
                              const float* __restrict__ embed) {
    __shared__ float xs[16][DIM];
    __shared__ unsigned long long wb[8][16];
    int nf = g_nflag; if (nf > FLAG_CAP) nf = FLAG_CAP;
    const int tid = threadIdx.x, wid = tid >> 5, lane = tid & 31;

    for (int base = blockIdx.y * 16; base < nf; base += 16 * 16) {
        int nrows = nf - base; if (nrows > 16) nrows = 16;
        __syncthreads();
        for (int i = tid; i < nrows * DIM; i += 256) {
            int r = i >> 8, d = i & 255;
            xs[r][d] = input[(size_t)g_flag[base + r] * DIM + d];
        }
        __syncthreads();

        int j0 = blockIdx.x * 1024 + tid;     // codes j0 + {0,256,512,768}
        float acc[4][16];
        #pragma unroll
        for (int q = 0; q < 4; ++q)
            #pragma unroll
            for (int r = 0; r < 16; ++r) acc[q][r] = 0.f;

        #pragma unroll 4
        for (int d = 0; d < DIM; ++d) {
            float e0 = embed[(size_t)d * NE + j0];
            float e1 = embed[(size_t)d * NE + j0 + 256];
            float e2 = embed[(size_t)d * NE + j0 + 512];
            float e3 = embed[(size_t)d * NE + j0 + 768];
            #pragma unroll
            for (int r = 0; r < 16; ++r) {
                float x = xs[r][d];
                acc[0][r] += e0 * x;
                acc[1][r] += e1 * x;
                acc[2][r] += e2 * x;
                acc[3][r] += e3 * x;
            }
        }
        float c0 = g_c[j0], c1 = g_c[j0 + 256], c2 = g_c[j0 + 512], c3 = g_c[j0 + 768];

        #pragma unroll 1
        for (int r = 0; r < 16; ++r) {
            float bv = acc[0][r] - c0; int bj = j0;
            float v1 = acc[1][r] - c1; if (v1 > bv) { bv = v1; bj = j0 + 256; }
            float v2 = acc[2][r] - c2; if (v2 > bv) { bv = v2; bj = j0 + 512; }
            float v3 = acc[3][r] - c3; if (v3 > bv) { bv = v3; bj = j0 + 768; }
            unsigned long long key = score_key(bv, bj);
            #pragma unroll
            for (int o = 16; o; o >>= 1) {
                unsigned long long other = __shfl_xor_sync(0xffffffffu, key, o);
                if (other > key) key = other;
            }
            if (lane == 0) wb[wid][r] = key;
        }
        __syncthreads();
        if (tid < nrows) {
            unsigned long long k = wb[0][tid];
            #pragma unroll
            for (int w = 1; w < 8; ++w) if (wb[w][tid] > k) k = wb[w][tid];
            atomicMax(&g_rkey[base + tid], k);
        }
    }
}

__global__ void extract_kernel() {
    int nf = g_nflag; if (nf > FLAG_CAP) nf = FLAG_CAP;
    for (int i = threadIdx.x; i < nf; i += 256) {
        unsigned long long k = g_rkey[i];
        g_idx[g_flag[i]] = (int)(0xFFFFFFFFu ^ (uint32_t)(k & 0xFFFFFFFFull));
    }
}

// ============================================================
// Output: gather, commitment loss, indices.
// ============================================================
__global__ void output_kernel(const float* __restrict__ input,
                              float* __restrict__ out, int write_extra) {
    int row  = blockIdx.x * 8 + (threadIdx.x >> 5);
    int lane = threadIdx.x & 31;
    int j = g_idx[row];
    const float4* x4 = reinterpret_cast<const float4*>(input + (size_t)row * DIM);
    const float4* e4 = reinterpret_cast<const float4*>(g_eT + (size_t)j * DIM);
    float4*       q4 = reinterpret_cast<float4*>(out + (size_t)row * DIM);
    float s = 0.f;
    #pragma unroll
    for (int t = 0; t < 2; ++t) {
        int d4 = lane + t * 32;
        float4 e = e4[d4];
        float4 x = x4[d4];
        q4[d4] = e;
        float a = e.x - x.x, b = e.y - x.y, c = e.z - x.z, d = e.w - x.w;
        s += a * a + b * b + c * c + d * d;
    }
    #pragma unroll
    for (int o = 16; o; o >>= 1) s += __shfl_xor_sync(0xffffffffu, s, o);
    if (lane == 0) {
        atomicAdd(&g_diff, (double)s);
        if (write_extra) out[(size_t)NROWS * DIM + 1 + row] = (float)j;
    }
}

__global__ void finalize_kernel(float* __restrict__ out, int write_extra) {
    if (write_extra)
        out[(size_t)NROWS * DIM] = (float)(g_diff * (1.0 / ((double)NROWS * (double)DIM)));
}

// ============================================================
extern "C" void kernel_launch(void* const* d_in, const int* in_sizes, int n_in,
                              void* d_out, int out_size) {
    const float* input = (const float*)d_in[0];
    const float* embed = (const float*)d_in[1];
    if (in_sizes[0] == NE * DIM && in_sizes[1] == NROWS * DIM) {
        input = (const float*)d_in[1];
        embed = (const float*)d_in[0];
    }
    float* out = (float*)d_out;
    int write_extra = (out_size >= NROWS * DIM + 1 + NROWS) ? 1 : 0;

    norms_part_kernel<<<dim3(NE / 256, 4), 256>>>(embed);
    norms_comb_kernel<<<NE / 256, 256>>>();
    transpose_kernel<<<dim3(NE / 32, DIM / 32), dim3(32, 8)>>>(embed);
    pack_kernel<<<DIM * NE / 256, 256>>>(embed);
    tc_argmin_kernel<<<NROWS / 64, 256>>>(input);
    rescue_kernel<<<dim3(8, 16), 256>>>(input, embed);
    extract_kernel<<<1, 256>>>();
    output_kernel<<<NROWS / 8, 256>>>(input, out, write_extra);
    finalize_kernel<<<1, 1>>>(out, write_extra);
}

// round 9
// speedup vs baseline: 1.2927x; 1.0718x over previous
#include <cuda_runtime.h>
#include <cuda_fp16.h>
#include <cstdint>

#define DIM    256
#define NE     8192
#define NROWS  32768
#define THRESH 0.04f
#define FLAG_CAP NROWS

// ---- device scratch ----
__device__ float  g_c[NE];                 // 0.5*||e_j||^2
__device__ float  g_cp[4][NE];             // norm partials (deterministic combine)
__device__ int    g_idx[NROWS];
__device__ float  g_eT[NE * DIM];          // fp32 transposed codebook (gather)
__device__ __half g_epk[NE * DIM];         // fp16 codebook, pre-packed MMA B-fragments
__device__ double g_diff;
__device__ int    g_nflag;
__device__ int    g_flag[FLAG_CAP];
__device__ unsigned long long g_rkey[FLAG_CAP];

__device__ __forceinline__ uint32_t smem_u32(const void* p) {
    uint32_t a;
    asm("{ .reg .u64 t; cvta.to.shared.u64 t, %1; cvt.u32.u64 %0, t; }" : "=r"(a) : "l"(p));
    return a;
}

__device__ __forceinline__ void ldmx4(uint32_t& r0, uint32_t& r1, uint32_t& r2, uint32_t& r3,
                                      uint32_t addr) {
    asm volatile("ldmatrix.sync.aligned.m8n8.x4.shared.b16 {%0,%1,%2,%3}, [%4];"
                 : "=r"(r0), "=r"(r1), "=r"(r2), "=r"(r3) : "r"(addr));
}

__device__ __forceinline__ void mma16816(float* c,
                                         const uint32_t* a,
                                         uint32_t b0, uint32_t b1) {
    asm volatile(
        "mma.sync.aligned.m16n8k16.row.col.f32.f16.f16.f32 "
        "{%0,%1,%2,%3}, {%4,%5,%6,%7}, {%8,%9}, {%0,%1,%2,%3};"
        : "+f"(c[0]), "+f"(c[1]), "+f"(c[2]), "+f"(c[3])
        : "r"(a[0]), "r"(a[1]), "r"(a[2]), "r"(a[3]), "r"(b0), "r"(b1));
}

// ============================================================
// Prep kernels
// ============================================================
__global__ void norms_part_kernel(const float* __restrict__ embed) {
    int j = blockIdx.x * 256 + threadIdx.x;
    int q = blockIdx.y;                    // dim quarter
    float s = 0.f;
    #pragma unroll 8
    for (int d = q * 64; d < q * 64 + 64; ++d) {
        float v = embed[(size_t)d * NE + j];
        s += v * v;
    }
    g_cp[q][j] = s;
}

__global__ void norms_comb_kernel() {
    int j = blockIdx.x * 256 + threadIdx.x;
    if (blockIdx.x == 0 && threadIdx.x == 0) { g_diff = 0.0; g_nflag = 0; }
    g_c[j] = 0.5f * (((g_cp[0][j] + g_cp[1][j]) + g_cp[2][j]) + g_cp[3][j]);
}

__global__ void transpose_kernel(const float* __restrict__ embed) {
    __shared__ float t[32][33];
    int j0 = blockIdx.x * 32;
    int d0 = blockIdx.y * 32;
    int tx = threadIdx.x, ty = threadIdx.y;   // 32 x 8
    #pragma unroll
    for (int i = 0; i < 32; i += 8)
        t[ty + i][tx] = embed[(size_t)(d0 + ty + i) * NE + (j0 + tx)];
    __syncthreads();
    #pragma unroll
    for (int i = 0; i < 32; i += 8)
        g_eT[(size_t)(j0 + ty + i) * DIM + (d0 + tx)] = t[tx][ty + i];
}

// Pack codebook into fp16 MMA B-fragments for direct LDG.128 loads.
// Warp unit (jt, ncol, g, p) = 512B: 32 lanes x 16B.
//   jt: 128-code tile; ncol in {0,1}: 64-code column; g: k32 group; p: n8 block.
// Lane l, 8 halves h0..h7:
//   n = p*8 + l/4;  k = g*32 + (kk), kk decomposed:
//   h = (kk>>3)*2 + (kk&1),  l%4 = (kk>>1)&3
//   => h0,h1 = b0 (k=(l%4)*2 +0,1); h2,h3 = b1 (k+8); h4..h7 same for k+16.
__global__ void pack_kernel(const float* __restrict__ embed) {
    int idx = blockIdx.x * 256 + threadIdx.x;    // over DIM*NE
    int d = idx >> 13;           // dim 0..255
    int j = idx & (NE - 1);      // code 0..8191
    float v = embed[idx];
    int jt = j >> 7;
    int ncol = (j >> 6) & 1;
    int p = (j >> 3) & 7;
    int nl = j & 7;
    int g = d >> 5;
    int kk = d & 31;
    int l = nl * 4 + ((kk >> 1) & 3);
    int h = ((kk >> 3) << 1) + (kk & 1);
    size_t unit = ((size_t)(jt * 2 + ncol) * 8 + g) * 8 + p;
    g_epk[unit * 256 + l * 8 + h] = __float2half(v);
}

// ============================================================
// Main HMMA kernel: 128 threads (4 warps = 2 mrow x 2 ncol), 32 rows/CTA,
// 1024 CTAs, 3 CTAs/SM. NO smem/barriers in main loop: B fragments
// loaded directly from pre-packed gmem via LDG.128, double-buffered.
// ============================================================
__global__ void __launch_bounds__(128, 3)
tc_argmin_kernel(const float* __restrict__ input) {
    __shared__ __align__(16) __half stage[8192];  // 16KB: 32-row A staging
    __shared__ float sbv[2][32];
    __shared__ float ssv[2][32];
    __shared__ int   sbi[2][32];

    const int tid  = threadIdx.x;
    const int wid  = tid >> 5;
    const int lane = tid & 31;
    const int mrow = wid >> 1;    // 0..1 : rows mrow*16..+15
    const int ncol = wid & 1;     // 0..1 : codes ncol*64..+63 within jt tile
    const int row0 = blockIdx.x * 32;
    const int mat  = lane >> 3;
    const int rr   = lane & 7;

    // ================= prologue: A fragments (32 rows staged once) =========
    uint32_t areg[64];   // 16 k16-chunks x 4
    {
        const int r = tid & 31;     // row
        const int p = tid >> 5;     // segment 0..3 (64 halves each)
        const float4* src = reinterpret_cast<const float4*>(
            input + (size_t)(row0 + r) * DIM + p * 64);
        #pragma unroll
        for (int u = 0; u < 8; ++u) {
            float4 fa = src[u * 2 + 0];
            float4 fb = src[u * 2 + 1];
            __half2 h0 = __floats2half2_rn(fa.x, fa.y);
            __half2 h1 = __floats2half2_rn(fa.z, fa.w);
            __half2 h2 = __floats2half2_rn(fb.x, fb.y);
            __half2 h3 = __floats2half2_rn(fb.z, fb.w);
            uint4 pk;
            pk.x = *reinterpret_cast<uint32_t*>(&h0);
            pk.y = *reinterpret_cast<uint32_t*>(&h1);
            pk.z = *reinterpret_cast<uint32_t*>(&h2);
            pk.w = *reinterpret_cast<uint32_t*>(&h3);
            int g = p * 8 + u;
            int swg = (g & 24) | ((g ^ r) & 7);
            *reinterpret_cast<uint4*>(
                reinterpret_cast<char*>(stage) + r * 512 + swg * 16) = pk;
        }
        __syncthreads();
        const int m = mrow * 16 + (mat & 1) * 8 + rr;
        #pragma unroll
        for (int c = 0; c < 16; ++c) {
            int g = c * 2 + (mat >> 1);
            int swg = (g & 24) | ((g ^ rr) & 7);
            uint32_t addr = smem_u32(stage) + (uint32_t)(m * 512 + swg * 16);
            ldmx4(areg[c * 4 + 0], areg[c * 4 + 1],
                  areg[c * 4 + 2], areg[c * 4 + 3], addr);
        }
    }

    // ================= main loop: LDG-direct B fragments ====================
    const uint4* bp = reinterpret_cast<const uint4*>(g_epk);

    float creg[32];
    float bb[2] = {-3.0e38f, -3.0e38f};
    float ss[2] = {-3.0e38f, -3.0e38f};
    int   ii[2] = {0, 0};

    uint4 b[2][2];
    // preload jt=0, chunk 0 (g=0, p=0,1)
    {
        int base = ncol * 2048 + lane;
        b[0][0] = bp[base];
        b[0][1] = bp[base + 32];
    }

    #pragma unroll 1
    for (int jt = 0; jt < 64; ++jt) {
        const int jbase = (jt * 2 + ncol) * 2048 + lane;

        #pragma unroll
        for (int q = 0; q < 32; ++q) creg[q] = 0.f;

        // 32 chunks: chunk q = (g = q>>2, p-pair = (q&3)*2). 2 LDG.128 + 4 MMA.
        #pragma unroll
        for (int q = 0; q < 32; ++q) {
            // prefetch next chunk (within jt, or jt+1 chunk 0)
            if (q < 31) {
                int nq = q + 1;
                int off = jbase + ((nq >> 2) * 8 + (nq & 3) * 2) * 32;
                b[nq & 1][0] = bp[off];
                b[nq & 1][1] = bp[off + 32];
            } else if (jt < 63) {
                int off = jbase + 2 * 2048;   // next jt, g=0, p=0
                b[0][0] = bp[off];
                b[0][1] = bp[off + 32];
            }
            const int g = q >> 2;
            const int p0 = (q & 3) * 2;
            const uint4 b0 = b[q & 1][0];
            const uint4 b1 = b[q & 1][1];
            mma16816(creg + p0 * 4,       areg + (2 * g) * 4,     b0.x, b0.y);
            mma16816(creg + p0 * 4,       areg + (2 * g + 1) * 4, b0.z, b0.w);
            mma16816(creg + (p0 + 1) * 4, areg + (2 * g) * 4,     b1.x, b1.y);
            mma16816(creg + (p0 + 1) * 4, areg + (2 * g + 1) * 4, b1.z, b1.w);
        }

        // epilogue: subtract 0.5||e||^2 (L1-resident) + running top-2
        const float2* cb = reinterpret_cast<const float2*>(g_c)
                         + jt * 64 + ncol * 32 + (lane & 3);
        #pragma unroll
        for (int p = 0; p < 8; ++p) {
            float2 c2 = __ldg(cb + p * 4);
            int n0 = jt * 128 + ncol * 64 + p * 8 + (lane & 3) * 2;
            float v;
            v = creg[p * 4 + 0] - c2.x;
            if (v > bb[0]) { ss[0] = bb[0]; bb[0] = v; ii[0] = n0; }
            else if (v > ss[0]) ss[0] = v;
            v = creg[p * 4 + 1] - c2.y;
            if (v > bb[0]) { ss[0] = bb[0]; bb[0] = v; ii[0] = n0 + 1; }
            else if (v > ss[0]) ss[0] = v;
            v = creg[p * 4 + 2] - c2.x;
            if (v > bb[1]) { ss[1] = bb[1]; bb[1] = v; ii[1] = n0; }
            else if (v > ss[1]) ss[1] = v;
            v = creg[p * 4 + 3] - c2.y;
            if (v > bb[1]) { ss[1] = bb[1]; bb[1] = v; ii[1] = n0 + 1; }
            else if (v > ss[1]) ss[1] = v;
        }
    }

    // ================= reduction: quad merge within warp =================
    #pragma unroll
    for (int sl = 0; sl < 2; ++sl) {
        float b2 = bb[sl], sec = ss[sl]; int i = ii[sl];
        #pragma unroll
        for (int off = 1; off <= 2; off <<= 1) {
            float ob = __shfl_xor_sync(0xffffffffu, b2, off);
            float os = __shfl_xor_sync(0xffffffffu, sec, off);
            int   oi = __shfl_xor_sync(0xffffffffu, i, off);
            if (ob > b2 || (ob == b2 && oi < i)) {
                sec = fmaxf(b2, os); b2 = ob; i = oi;
            } else {
                sec = fmaxf(sec, ob);
            }
        }
        if ((lane & 3) == 0) {
            int lrow = mrow * 16 + (lane >> 2) + sl * 8;
            sbv[ncol][lrow] = b2;
            ssv[ncol][lrow] = sec;
            sbi[ncol][lrow] = i;
        }
    }
    __syncthreads();

    // merge the two n-columns per row; write index; flag narrow margins
    if (tid < 32) {
        float va = sbv[0][tid], vb = sbv[1][tid];
        float sa = ssv[0][tid], sb = ssv[1][tid];
        int   ia = sbi[0][tid], ib = sbi[1][tid];
        float bv, sec; int bi;
        if (va > vb || (va == vb && ia < ib)) { bv = va; bi = ia; sec = fmaxf(vb, sa); }
        else                                   { bv = vb; bi = ib; sec = fmaxf(va, sb); }
        int row = row0 + tid;
        g_idx[row] = bi;
        if (bv - sec < THRESH) {
            int sidx = atomicAdd(&g_nflag, 1);
            if (sidx < FLAG_CAP) { g_flag[sidx] = row; g_rkey[sidx] = 0ull; }
        }
    }
}

// ============================================================
// Exact fp32 rescue for narrow-margin rows.
// ============================================================
__device__ __forceinline__ unsigned long long score_key(float v, int j) {
    uint32_t u = __float_as_uint(v);
    u = (u & 0x80000000u) ? ~u : (u | 0x80000000u);
    return ((unsigned long long)u << 32) | (uint32_t)(0xFFFFFFFFu ^ (uint32_t)j);
}

__global__ void rescue_kernel(const float* __restrict__ input,
                              const float* __restrict__ embed) {
    __shared__ float xs[16][DIM];
    __shared__ unsigned long long wb[8][16];
    int nf = g_nflag; if (nf > FLAG_CAP) nf = FLAG_CAP;
    const int tid = threadIdx.x, wid = tid >> 5, lane = tid & 31;

    for (int base = blockIdx.y * 16; base < nf; base += 16 * 16) {
        int nrows = nf - base; if (nrows > 16) nrows = 16;
        __syncthreads();
        for (int i = tid; i < nrows * DIM; i += 256) {
            int r = i >> 8, d = i & 255;
            xs[r][d] = input[(size_t)g_flag[base + r] * DIM + d];
        }
        __syncthreads();

        int j0 = blockIdx.x * 1024 + tid;     // codes j0 + {0,256,512,768}
        float acc[4][16];
        #pragma unroll
        for (int q = 0; q < 4; ++q)
            #pragma unroll
            for (int r = 0; r < 16; ++r) acc[q][r] = 0.f;

        #pragma unroll 4
        for (int d = 0; d < DIM; ++d) {
            float e0 = embed[(size_t)d * NE + j0];
            float e1 = embed[(size_t)d * NE + j0 + 256];
            float e2 = embed[(size_t)d * NE + j0 + 512];
            float e3 = embed[(size_t)d * NE + j0 + 768];
            #pragma unroll
            for (int r = 0; r < 16; ++r) {
                float x = xs[r][d];
                acc[0][r] += e0 * x;
                acc[1][r] += e1 * x;
                acc[2][r] += e2 * x;
                acc[3][r] += e3 * x;
            }
        }
        float c0 = g_c[j0], c1 = g_c[j0 + 256], c2 = g_c[j0 + 512], c3 = g_c[j0 + 768];

        #pragma unroll 1
        for (int r = 0; r < 16; ++r) {
            float bv = acc[0][r] - c0; int bj = j0;
            float v1 = acc[1][r] - c1; if (v1 > bv) { bv = v1; bj = j0 + 256; }
            float v2 = acc[2][r] - c2; if (v2 > bv) { bv = v2; bj = j0 + 512; }
            float v3 = acc[3][r] - c3; if (v3 > bv) { bv = v3; bj = j0 + 768; }
            unsigned long long key = score_key(bv, bj);
            #pragma unroll
            for (int o = 16; o; o >>= 1) {
                unsigned long long other = __shfl_xor_sync(0xffffffffu, key, o);
                if (other > key) key = other;
            }
            if (lane == 0) wb[wid][r] = key;
        }
        __syncthreads();
        if (tid < nrows) {
            unsigned long long k = wb[0][tid];
            #pragma unroll
            for (int w = 1; w < 8; ++w) if (wb[w][tid] > k) k = wb[w][tid];
            atomicMax(&g_rkey[base + tid], k);
        }
    }
}

__global__ void extract_kernel() {
    int nf = g_nflag; if (nf > FLAG_CAP) nf = FLAG_CAP;
    for (int i = threadIdx.x; i < nf; i += 256) {
        unsigned long long k = g_rkey[i];
        g_idx[g_flag[i]] = (int)(0xFFFFFFFFu ^ (uint32_t)(k & 0xFFFFFFFFull));
    }
}

// ============================================================
// Output: gather, commitment loss, indices.
// ============================================================
__global__ void output_kernel(const float* __restrict__ input,
                              float* __restrict__ out, int write_extra) {
    int row  = blockIdx.x * 8 + (threadIdx.x >> 5);
    int lane = threadIdx.x & 31;
    int j = g_idx[row];
    const float4* x4 = reinterpret_cast<const float4*>(input + (size_t)row * DIM);
    const float4* e4 = reinterpret_cast<const float4*>(g_eT + (size_t)j * DIM);
    float4*       q4 = reinterpret_cast<float4*>(out + (size_t)row * DIM);
    float s = 0.f;
    #pragma unroll
    for (int t = 0; t < 2; ++t) {
        int d4 = lane + t * 32;
        float4 e = e4[d4];
        float4 x = x4[d4];
        q4[d4] = e;
        float a = e.x - x.x, b = e.y - x.y, c = e.z - x.z, d = e.w - x.w;
        s += a * a + b * b + c * c + d * d;
    }
    #pragma unroll
    for (int o = 16; o; o >>= 1) s += __shfl_xor_sync(0xffffffffu, s, o);
    if (lane == 0) {
        atomicAdd(&g_diff, (double)s);
        if (write_extra) out[(size_t)NROWS * DIM + 1 + row] = (float)j;
    }
}

__global__ void finalize_kernel(float* __restrict__ out, int write_extra) {
    if (write_extra)
        out[(size_t)NROWS * DIM] = (float)(g_diff * (1.0 / ((double)NROWS * (double)DIM)));
}

// ============================================================
extern "C" void kernel_launch(void* const* d_in, const int* in_sizes, int n_in,
                              void* d_out, int out_size) {
    const float* input = (const float*)d_in[0];
    const float* embed = (const float*)d_in[1];
    if (in_sizes[0] == NE * DIM && in_sizes[1] == NROWS * DIM) {
        input = (const float*)d_in[1];
        embed = (const float*)d_in[0];
    }
    float* out = (float*)d_out;
    int write_extra = (out_size >= NROWS * DIM + 1 + NROWS) ? 1 : 0;

    norms_part_kernel<<<dim3(NE / 256, 4), 256>>>(embed);
    norms_comb_kernel<<<NE / 256, 256>>>();
    transpose_kernel<<<dim3(NE / 32, DIM / 32), dim3(32, 8)>>>(embed);
    pack_kernel<<<DIM * NE / 256, 256>>>(embed);
    tc_argmin_kernel<<<NROWS / 32, 128>>>(input);
    rescue_kernel<<<dim3(8, 16), 256>>>(input, embed);
    extract_kernel<<<1, 256>>>();
    output_kernel<<<NROWS / 8, 256>>>(input, out, write_extra);
    finalize_kernel<<<1, 1>>>(out, write_extra);
}

// round 10
// speedup vs baseline: 1.4855x; 1.1492x over previous
#include <cuda_runtime.h>
#include <cuda_fp16.h>
#include <cstdint>

#define DIM    256
#define NE     8192
#define NROWS  32768
#define THRESH 0.04f
#define FLAG_CAP NROWS

// ---- device scratch ----
__device__ float  g_c[NE];                 // 0.5*||e_j||^2
__device__ float  g_cp[4][NE];             // norm partials (deterministic combine)
__device__ int    g_idx[NROWS];
__device__ float  g_eT[NE * DIM];          // fp32 transposed codebook (gather)
__device__ __half g_epk[NE * DIM];         // fp16 codebook, pre-packed MMA B-fragments
__device__ double g_diff;
__device__ int    g_nflag;
__device__ int    g_flag[FLAG_CAP];
__device__ unsigned long long g_rkey[FLAG_CAP];

__device__ __forceinline__ uint32_t smem_u32(const void* p) {
    uint32_t a;
    asm("{ .reg .u64 t; cvta.to.shared.u64 t, %1; cvt.u32.u64 %0, t; }" : "=r"(a) : "l"(p));
    return a;
}

__device__ __forceinline__ void ldmx4(uint32_t& r0, uint32_t& r1, uint32_t& r2, uint32_t& r3,
                                      uint32_t addr) {
    asm volatile("ldmatrix.sync.aligned.m8n8.x4.shared.b16 {%0,%1,%2,%3}, [%4];"
                 : "=r"(r0), "=r"(r1), "=r"(r2), "=r"(r3) : "r"(addr));
}

__device__ __forceinline__ void mma16816(float* c,
                                         const uint32_t* a,
                                         uint32_t b0, uint32_t b1) {
    asm volatile(
        "mma.sync.aligned.m16n8k16.row.col.f32.f16.f16.f32 "
        "{%0,%1,%2,%3}, {%4,%5,%6,%7}, {%8,%9}, {%0,%1,%2,%3};"
        : "+f"(c[0]), "+f"(c[1]), "+f"(c[2]), "+f"(c[3])
        : "r"(a[0]), "r"(a[1]), "r"(a[2]), "r"(a[3]), "r"(b0), "r"(b1));
}

// ============================================================
// Prep kernels
// ============================================================
__global__ void norms_part_kernel(const float* __restrict__ embed) {
    int j = blockIdx.x * 256 + threadIdx.x;
    int q = blockIdx.y;                    // dim quarter
    float s = 0.f;
    #pragma unroll 8
    for (int d = q * 64; d < q * 64 + 64; ++d) {
        float v = embed[(size_t)d * NE + j];
        s += v * v;
    }
    g_cp[q][j] = s;
}

__global__ void norms_comb_kernel() {
    int j = blockIdx.x * 256 + threadIdx.x;
    if (blockIdx.x == 0 && threadIdx.x == 0) { g_diff = 0.0; g_nflag = 0; }
    g_c[j] = 0.5f * (((g_cp[0][j] + g_cp[1][j]) + g_cp[2][j]) + g_cp[3][j]);
}

__global__ void transpose_kernel(const float* __restrict__ embed) {
    __shared__ float t[32][33];
    int j0 = blockIdx.x * 32;
    int d0 = blockIdx.y * 32;
    int tx = threadIdx.x, ty = threadIdx.y;   // 32 x 8
    #pragma unroll
    for (int i = 0; i < 32; i += 8)
        t[ty + i][tx] = embed[(size_t)(d0 + ty + i) * NE + (j0 + tx)];
    __syncthreads();
    #pragma unroll
    for (int i = 0; i < 32; i += 8)
        g_eT[(size_t)(j0 + ty + i) * DIM + (d0 + tx)] = t[tx][ty + i];
}

// Pack codebook into fp16 MMA B-fragments for direct LDG.128 loads.
// Unit (jt, ncol, g, p) = 512B: n8 x k32 fragment (32 lanes x 16B).
// Lane l = nl*4 + ((kk>>1)&3), halves h = (kk>>3)*2 + (kk&1).
__global__ void pack_kernel(const float* __restrict__ embed) {
    int idx = blockIdx.x * 256 + threadIdx.x;    // over DIM*NE
    int d = idx >> 13;           // dim 0..255
    int j = idx & (NE - 1);      // code 0..8191
    float v = embed[idx];
    int jt = j >> 7;
    int ncol = (j >> 6) & 1;
    int p = (j >> 3) & 7;
    int nl = j & 7;
    int g = d >> 5;
    int kk = d & 31;
    int l = nl * 4 + ((kk >> 1) & 3);
    int h = ((kk >> 3) << 1) + (kk & 1);
    size_t unit = ((size_t)(jt * 2 + ncol) * 8 + g) * 8 + p;
    g_epk[unit * 256 + l * 8 + h] = __float2half(v);
}

// ============================================================
// Main HMMA kernel: 128 threads (4 warps), 32 rows/CTA, 1024 CTAs.
// Each warp: m32 (2 m16 tiles, SAME rows as siblings) x a DISTINCT
// 2048-code quarter -> zero B duplication; one B LDG feeds 4 MMAs.
// Chip B traffic halves vs R9 (4.2 GB), attacking the LTS wall.
// ============================================================
__global__ void __launch_bounds__(128, 2)
tc_argmin_kernel(const float* __restrict__ input) {
    __shared__ __align__(16) __half stage[8192];  // 16KB: 32-row A staging
    __shared__ float sbv[4][32];
    __shared__ float ssv[4][32];
    __shared__ int   sbi[4][32];

    const int tid  = threadIdx.x;
    const int wid  = tid >> 5;    // warp = code quarter
    const int lane = tid & 31;
    const int row0 = blockIdx.x * 32;
    const int mat  = lane >> 3;
    const int rr   = lane & 7;

    // ================= prologue: A fragments (both m16 tiles) ==============
    uint32_t areg[128];   // 2 m-tiles x 16 k16-chunks x 4
    {
        const int r = tid & 31;     // row
        const int p = tid >> 5;     // segment 0..3 (64 halves each)
        const float4* src = reinterpret_cast<const float4*>(
            input + (size_t)(row0 + r) * DIM + p * 64);
        #pragma unroll
        for (int u = 0; u < 8; ++u) {
            float4 fa = src[u * 2 + 0];
            float4 fb = src[u * 2 + 1];
            __half2 h0 = __floats2half2_rn(fa.x, fa.y);
            __half2 h1 = __floats2half2_rn(fa.z, fa.w);
            __half2 h2 = __floats2half2_rn(fb.x, fb.y);
            __half2 h3 = __floats2half2_rn(fb.z, fb.w);
            uint4 pk;
            pk.x = *reinterpret_cast<uint32_t*>(&h0);
            pk.y = *reinterpret_cast<uint32_t*>(&h1);
            pk.z = *reinterpret_cast<uint32_t*>(&h2);
            pk.w = *reinterpret_cast<uint32_t*>(&h3);
            int g = p * 8 + u;
            int swg = (g & 24) | ((g ^ r) & 7);
            *reinterpret_cast<uint4*>(
                reinterpret_cast<char*>(stage) + r * 512 + swg * 16) = pk;
        }
        __syncthreads();
        #pragma unroll
        for (int mt = 0; mt < 2; ++mt) {
            const int m = mt * 16 + (mat & 1) * 8 + rr;
            #pragma unroll
            for (int c = 0; c < 16; ++c) {
                int g = c * 2 + (mat >> 1);
                int swg = (g & 24) | ((g ^ rr) & 7);
                uint32_t addr = smem_u32(stage) + (uint32_t)(m * 512 + swg * 16);
                ldmx4(areg[mt * 64 + c * 4 + 0], areg[mt * 64 + c * 4 + 1],
                      areg[mt * 64 + c * 4 + 2], areg[mt * 64 + c * 4 + 3], addr);
            }
        }
    }

    // ================= main loop: LDG-direct B, 4-slot prefetch ring ========
    const uint4* bp = reinterpret_cast<const uint4*>(g_epk);
    const int q = wid;

    float bb[4] = {-3.0e38f, -3.0e38f, -3.0e38f, -3.0e38f};
    float ss[4] = {-3.0e38f, -3.0e38f, -3.0e38f, -3.0e38f};
    int   ii[4] = {0, 0, 0, 0};

    uint4 br[4];
    {
        int id0 = q * 256;
        int b0 = ((id0 >> 3) * 64 + (id0 & 7)) * 32 + lane;
        br[0] = bp[b0];
        br[1] = bp[b0 + 256];
        br[2] = bp[b0 + 512];
        br[3] = bp[b0 + 768];
    }

    #pragma unroll 1
    for (int u = 0; u < 256; ++u) {
        const int id    = q * 256 + u;
        const int base  = ((id >> 3) * 64 + (id & 7)) * 32 + lane;
        const int idn   = id + 1;
        const int basen = (u < 255) ? ((idn >> 3) * 64 + (idn & 7)) * 32 + lane : base;

        float creg[8];
        #pragma unroll
        for (int z = 0; z < 8; ++z) creg[z] = 0.f;

        #pragma unroll
        for (int g = 0; g < 8; ++g) {
            const uint4 b = br[g & 3];
            // prefetch step t+4 into the slot just consumed
            const int paddr = (g < 4) ? (base + (g + 4) * 256)
                                      : (basen + (g - 4) * 256);
            br[g & 3] = bp[paddr];
            mma16816(creg + 0, areg + (2 * g) * 4,          b.x, b.y);
            mma16816(creg + 0, areg + (2 * g + 1) * 4,      b.z, b.w);
            mma16816(creg + 4, areg + 64 + (2 * g) * 4,     b.x, b.y);
            mma16816(creg + 4, areg + 64 + (2 * g + 1) * 4, b.z, b.w);
        }

        // epilogue per n8: subtract 0.5||e||^2 + running top-2 (4 slots)
        float2 c2 = __ldg(reinterpret_cast<const float2*>(g_c) + id * 4 + (lane & 3));
        int n0 = id * 8 + (lane & 3) * 2;
        float v;
        v = creg[0] - c2.x;
        if (v > bb[0]) { ss[0] = bb[0]; bb[0] = v; ii[0] = n0; } else if (v > ss[0]) ss[0] = v;
        v = creg[1] - c2.y;
        if (v > bb[0]) { ss[0] = bb[0]; bb[0] = v; ii[0] = n0 + 1; } else if (v > ss[0]) ss[0] = v;
        v = creg[2] - c2.x;
        if (v > bb[1]) { ss[1] = bb[1]; bb[1] = v; ii[1] = n0; } else if (v > ss[1]) ss[1] = v;
        v = creg[3] - c2.y;
        if (v > bb[1]) { ss[1] = bb[1]; bb[1] = v; ii[1] = n0 + 1; } else if (v > ss[1]) ss[1] = v;
        v = creg[4] - c2.x;
        if (v > bb[2]) { ss[2] = bb[2]; bb[2] = v; ii[2] = n0; } else if (v > ss[2]) ss[2] = v;
        v = creg[5] - c2.y;
        if (v > bb[2]) { ss[2] = bb[2]; bb[2] = v; ii[2] = n0 + 1; } else if (v > ss[2]) ss[2] = v;
        v = creg[6] - c2.x;
        if (v > bb[3]) { ss[3] = bb[3]; bb[3] = v; ii[3] = n0; } else if (v > ss[3]) ss[3] = v;
        v = creg[7] - c2.y;
        if (v > bb[3]) { ss[3] = bb[3]; bb[3] = v; ii[3] = n0 + 1; } else if (v > ss[3]) ss[3] = v;
    }

    // ================= reduction =================
    // quad merge within warp (lanes 0..3 of each quad hold different codes)
    #pragma unroll
    for (int sl = 0; sl < 4; ++sl) {
        float b2 = bb[sl], sec = ss[sl]; int i = ii[sl];
        #pragma unroll
        for (int off = 1; off <= 2; off <<= 1) {
            float ob = __shfl_xor_sync(0xffffffffu, b2, off);
            float os = __shfl_xor_sync(0xffffffffu, sec, off);
            int   oi = __shfl_xor_sync(0xffffffffu, i, off);
            if (ob > b2 || (ob == b2 && oi < i)) {
                sec = fmaxf(b2, os); b2 = ob; i = oi;
            } else {
                sec = fmaxf(sec, ob);
            }
        }
        if ((lane & 3) == 0) {
            int lrow = (sl >> 1) * 16 + (sl & 1) * 8 + (lane >> 2);
            sbv[wid][lrow] = b2;
            ssv[wid][lrow] = sec;
            sbi[wid][lrow] = i;
        }
    }
    __syncthreads();

    // merge 4 warps (disjoint code quarters) per row; write + flag
    if (tid < 32) {
        float va = sbv[0][tid], sa = ssv[0][tid];
        int   ia = sbi[0][tid];
        #pragma unroll
        for (int w = 1; w < 4; ++w) {
            float vb = sbv[w][tid], sb = ssv[w][tid];
            int   ib = sbi[w][tid];
            if (vb > va || (vb == va && ib < ia)) {
                sa = fmaxf(va, sb); va = vb; ia = ib;
            } else {
                sa = fmaxf(sa, vb);
            }
        }
        int row = row0 + tid;
        g_idx[row] = ia;
        if (va - sa < THRESH) {
            int sidx = atomicAdd(&g_nflag, 1);
            if (sidx < FLAG_CAP) { g_flag[sidx] = row; g_rkey[sidx] = 0ull; }
        }
    }
}

// ============================================================
// Exact fp32 rescue for narrow-margin rows.
// ============================================================
__device__ __forceinline__ unsigned long long score_key(float v, int j) {
    uint32_t u = __float_as_uint(v);
    u = (u & 0x80000000u) ? ~u : (u | 0x80000000u);
    return ((unsigned long long)u << 32) | (uint32_t)(0xFFFFFFFFu ^ (uint32_t)j);
}

__global__ void rescue_kernel(const float* __restrict__ input,
                              const float* __restrict__ embed) {
    __shared__ float xs[16][DIM];
    __shared__ unsigned long long wb[8][16];
    int nf = g_nflag; if (nf > FLAG_CAP) nf = FLAG_CAP;
    const int tid = threadIdx.x, wid = tid >> 5, lane = tid & 31;

    for (int base = blockIdx.y * 16; base < nf; base += 16 * 16) {
        int nrows = nf - base; if (nrows > 16) nrows = 16;
        __syncthreads();
        for (int i = tid; i < nrows * DIM; i += 256) {
            int r = i >> 8, d = i & 255;
            xs[r][d] = input[(size_t)g_flag[base + r] * DIM + d];
        }
        __syncthreads();

        int j0 = blockIdx.x * 1024 + tid;     // codes j0 + {0,256,512,768}
        float acc[4][16];
        #pragma unroll
        for (int qq = 0; qq < 4; ++qq)
            #pragma unroll
            for (int r = 0; r < 16; ++r) acc[qq][r] = 0.f;

        #pragma unroll 4
        for (int d = 0; d < DIM; ++d) {
            float e0 = embed[(size_t)d * NE + j0];
            float e1 = embed[(size_t)d * NE + j0 + 256];
            float e2 = embed[(size_t)d * NE + j0 + 512];
            float e3 = embed[(size_t)d * NE + j0 + 768];
            #pragma unroll
            for (int r = 0; r < 16; ++r) {
                float x = xs[r][d];
                acc[0][r] += e0 * x;
                acc[1][r] += e1 * x;
                acc[2][r] += e2 * x;
                acc[3][r] += e3 * x;
            }
        }
        float c0 = g_c[j0], c1 = g_c[j0 + 256], c2 = g_c[j0 + 512], c3 = g_c[j0 + 768];

        #pragma unroll 1
        for (int r = 0; r < 16; ++r) {
            float bv = acc[0][r] - c0; int bj = j0;
            float v1 = acc[1][r] - c1; if (v1 > bv) { bv = v1; bj = j0 + 256; }
            float v2 = acc[2][r] - c2; if (v2 > bv) { bv = v2; bj = j0 + 512; }
            float v3 = acc[3][r] - c3; if (v3 > bv) { bv = v3; bj = j0 + 768; }
            unsigned long long key = score_key(bv, bj);
            #pragma unroll
            for (int o = 16; o; o >>= 1) {
                unsigned long long other = __shfl_xor_sync(0xffffffffu, key, o);
                if (other > key) key = other;
            }
            if (lane == 0) wb[wid][r] = key;
        }
        __syncthreads();
        if (tid < nrows) {
            unsigned long long k = wb[0][tid];
            #pragma unroll
            for (int w = 1; w < 8; ++w) if (wb[w][tid] > k) k = wb[w][tid];
            atomicMax(&g_rkey[base + tid], k);
        }
    }
}

__global__ void extract_kernel() {
    int nf = g_nflag; if (nf > FLAG_CAP) nf = FLAG_CAP;
    for (int i = threadIdx.x; i < nf; i += 256) {
        unsigned long long k = g_rkey[i];
        g_idx[g_flag[i]] = (int)(0xFFFFFFFFu ^ (uint32_t)(k & 0xFFFFFFFFull));
    }
}

// ============================================================
// Output: gather, commitment loss, indices.
// ============================================================
__global__ void output_kernel(const float* __restrict__ input,
                              float* __restrict__ out, int write_extra) {
    int row  = blockIdx.x * 8 + (threadIdx.x >> 5);
    int lane = threadIdx.x & 31;
    int j = g_idx[row];
    const float4* x4 = reinterpret_cast<const float4*>(input + (size_t)row * DIM);
    const float4* e4 = reinterpret_cast<const float4*>(g_eT + (size_t)j * DIM);
    float4*       q4 = reinterpret_cast<float4*>(out + (size_t)row * DIM);
    float s = 0.f;
    #pragma unroll
    for (int t = 0; t < 2; ++t) {
        int d4 = lane + t * 32;
        float4 e = e4[d4];
        float4 x = x4[d4];
        q4[d4] = e;
        float a = e.x - x.x, b = e.y - x.y, c = e.z - x.z, d = e.w - x.w;
        s += a * a + b * b + c * c + d * d;
    }
    #pragma unroll
    for (int o = 16; o; o >>= 1) s += __shfl_xor_sync(0xffffffffu, s, o);
    if (lane == 0) {
        atomicAdd(&g_diff, (double)s);
        if (write_extra) out[(size_t)NROWS * DIM + 1 + row] = (float)j;
    }
}

__global__ void finalize_kernel(float* __restrict__ out, int write_extra) {
    if (write_extra)
        out[(size_t)NROWS * DIM] = (float)(g_diff * (1.0 / ((double)NROWS * (double)DIM)));
}

// ============================================================
extern "C" void kernel_launch(void* const* d_in, const int* in_sizes, int n_in,
                              void* d_out, int out_size) {
    const float* input = (const float*)d_in[0];
    const float* embed = (const float*)d_in[1];
    if (in_sizes[0] == NE * DIM && in_sizes[1] == NROWS * DIM) {
        input = (const float*)d_in[1];
        embed = (const float*)d_in[0];
    }
    float* out = (float*)d_out;
    int write_extra = (out_size >= NROWS * DIM + 1 + NROWS) ? 1 : 0;

    norms_part_kernel<<<dim3(NE / 256, 4), 256>>>(embed);
    norms_comb_kernel<<<NE / 256, 256>>>();
    transpose_kernel<<<dim3(NE / 32, DIM / 32), dim3(32, 8)>>>(embed);
    pack_kernel<<<DIM * NE / 256, 256>>>(embed);
    tc_argmin_kernel<<<NROWS / 32, 128>>>(input);
    rescue_kernel<<<dim3(8, 16), 256>>>(input, embed);
    extract_kernel<<<1, 256>>>();
    output_kernel<<<NROWS / 8, 256>>>(input, out, write_extra);
    finalize_kernel<<<1, 1>>>(out, write_extra);
}

// round 11
// speedup vs baseline: 1.5049x; 1.0131x over previous
#include <cuda_runtime.h>
#include <cuda_fp16.h>
#include <cstdint>

#define DIM    256
#define NE     8192
#define NROWS  32768
#define THRESH 0.04f
#define FLAG_CAP NROWS

// ---- device scratch ----
__device__ float  g_c[NE];                 // 0.5*||e_j||^2
__device__ float  g_cp[4][NE];             // norm partials (deterministic combine)
__device__ int    g_idx[NROWS];
__device__ float  g_eT[NE * DIM];          // fp32 transposed codebook (gather)
__device__ __half g_epk[NE * DIM];         // fp16 codebook, pre-packed MMA B-fragments
__device__ double g_diff;
__device__ int    g_nflag;
__device__ int    g_flag[FLAG_CAP];
__device__ unsigned long long g_rkey[FLAG_CAP];

__device__ __forceinline__ uint32_t smem_u32(const void* p) {
    uint32_t a;
    asm("{ .reg .u64 t; cvta.to.shared.u64 t, %1; cvt.u32.u64 %0, t; }" : "=r"(a) : "l"(p));
    return a;
}

__device__ __forceinline__ void ldmx4(uint32_t& r0, uint32_t& r1, uint32_t& r2, uint32_t& r3,
                                      uint32_t addr) {
    asm volatile("ldmatrix.sync.aligned.m8n8.x4.shared.b16 {%0,%1,%2,%3}, [%4];"
                 : "=r"(r0), "=r"(r1), "=r"(r2), "=r"(r3) : "r"(addr));
}

__device__ __forceinline__ void mma16816(float* c,
                                         const uint32_t* a,
                                         uint32_t b0, uint32_t b1) {
    asm volatile(
        "mma.sync.aligned.m16n8k16.row.col.f32.f16.f16.f32 "
        "{%0,%1,%2,%3}, {%4,%5,%6,%7}, {%8,%9}, {%0,%1,%2,%3};"
        : "+f"(c[0]), "+f"(c[1]), "+f"(c[2]), "+f"(c[3])
        : "r"(a[0]), "r"(a[1]), "r"(a[2]), "r"(a[3]), "r"(b0), "r"(b1));
}

// ============================================================
// Prep kernels
// ============================================================
__global__ void norms_part_kernel(const float* __restrict__ embed) {
    int j = blockIdx.x * 256 + threadIdx.x;
    int q = blockIdx.y;                    // dim quarter
    float s = 0.f;
    #pragma unroll 8
    for (int d = q * 64; d < q * 64 + 64; ++d) {
        float v = embed[(size_t)d * NE + j];
        s += v * v;
    }
    g_cp[q][j] = s;
}

__global__ void norms_comb_kernel() {
    int j = blockIdx.x * 256 + threadIdx.x;
    if (blockIdx.x == 0 && threadIdx.x == 0) { g_diff = 0.0; g_nflag = 0; }
    g_c[j] = 0.5f * (((g_cp[0][j] + g_cp[1][j]) + g_cp[2][j]) + g_cp[3][j]);
}

__global__ void transpose_kernel(const float* __restrict__ embed) {
    __shared__ float t[32][33];
    int j0 = blockIdx.x * 32;
    int d0 = blockIdx.y * 32;
    int tx = threadIdx.x, ty = threadIdx.y;   // 32 x 8
    #pragma unroll
    for (int i = 0; i < 32; i += 8)
        t[ty + i][tx] = embed[(size_t)(d0 + ty + i) * NE + (j0 + tx)];
    __syncthreads();
    #pragma unroll
    for (int i = 0; i < 32; i += 8)
        g_eT[(size_t)(j0 + ty + i) * DIM + (d0 + tx)] = t[tx][ty + i];
}

// Pack codebook into fp16 MMA B-fragments for direct LDG.128 loads.
// Unit (jt, ncol, g, p) = 512B: n8 x k32 fragment (32 lanes x 16B).
// Lane l = nl*4 + ((kk>>1)&3), halves h = (kk>>3)*2 + (kk&1).
__global__ void pack_kernel(const float* __restrict__ embed) {
    int idx = blockIdx.x * 256 + threadIdx.x;    // over DIM*NE
    int d = idx >> 13;           // dim 0..255
    int j = idx & (NE - 1);      // code 0..8191
    float v = embed[idx];
    int jt = j >> 7;
    int ncol = (j >> 6) & 1;
    int p = (j >> 3) & 7;
    int nl = j & 7;
    int g = d >> 5;
    int kk = d & 31;
    int l = nl * 4 + ((kk >> 1) & 3);
    int h = ((kk >> 3) << 1) + (kk & 1);
    size_t unit = ((size_t)(jt * 2 + ncol) * 8 + g) * 8 + p;
    g_epk[unit * 256 + l * 8 + h] = __float2half(v);
}

// ============================================================
// Main HMMA kernel: 128 threads (4 warps), 32 rows/CTA, 1024 CTAs.
// Warp: m32 x distinct 2048-code quarter; B via LDG-direct with a
// UNIFORM distance-8 prefetch ring (slot g reloaded with next-u same-g).
// ============================================================
__global__ void __launch_bounds__(128, 2)
tc_argmin_kernel(const float* __restrict__ input) {
    __shared__ __align__(16) __half stage[8192];  // 16KB: 32-row A staging
    __shared__ float sbv[4][32];
    __shared__ float ssv[4][32];
    __shared__ int   sbi[4][32];

    const int tid  = threadIdx.x;
    const int wid  = tid >> 5;    // warp = code quarter
    const int lane = tid & 31;
    const int row0 = blockIdx.x * 32;
    const int mat  = lane >> 3;
    const int rr   = lane & 7;

    // ================= prologue: A fragments (both m16 tiles) ==============
    uint32_t areg[128];   // 2 m-tiles x 16 k16-chunks x 4
    {
        const int r = tid & 31;     // row
        const int p = tid >> 5;     // segment 0..3 (64 halves each)
        const float4* src = reinterpret_cast<const float4*>(
            input + (size_t)(row0 + r) * DIM + p * 64);
        #pragma unroll
        for (int u = 0; u < 8; ++u) {
            float4 fa = src[u * 2 + 0];
            float4 fb = src[u * 2 + 1];
            __half2 h0 = __floats2half2_rn(fa.x, fa.y);
            __half2 h1 = __floats2half2_rn(fa.z, fa.w);
            __half2 h2 = __floats2half2_rn(fb.x, fb.y);
            __half2 h3 = __floats2half2_rn(fb.z, fb.w);
            uint4 pk;
            pk.x = *reinterpret_cast<uint32_t*>(&h0);
            pk.y = *reinterpret_cast<uint32_t*>(&h1);
            pk.z = *reinterpret_cast<uint32_t*>(&h2);
            pk.w = *reinterpret_cast<uint32_t*>(&h3);
            int g = p * 8 + u;
            int swg = (g & 24) | ((g ^ r) & 7);
            *reinterpret_cast<uint4*>(
                reinterpret_cast<char*>(stage) + r * 512 + swg * 16) = pk;
        }
        __syncthreads();
        #pragma unroll
        for (int mt = 0; mt < 2; ++mt) {
            const int m = mt * 16 + (mat & 1) * 8 + rr;
            #pragma unroll
            for (int c = 0; c < 16; ++c) {
                int g = c * 2 + (mat >> 1);
                int swg = (g & 24) | ((g ^ rr) & 7);
                uint32_t addr = smem_u32(stage) + (uint32_t)(m * 512 + swg * 16);
                ldmx4(areg[mt * 64 + c * 4 + 0], areg[mt * 64 + c * 4 + 1],
                      areg[mt * 64 + c * 4 + 2], areg[mt * 64 + c * 4 + 3], addr);
            }
        }
    }

    // ================= main loop: LDG-direct B, distance-8 ring ============
    const uint4* bp = reinterpret_cast<const uint4*>(g_epk);
    const int q = wid;

    float bb[4] = {-3.0e38f, -3.0e38f, -3.0e38f, -3.0e38f};
    float ss[4] = {-3.0e38f, -3.0e38f, -3.0e38f, -3.0e38f};
    int   ii[4] = {0, 0, 0, 0};

    uint4 br[8];   // full u-chunk in flight: slot g holds (u, g)
    {
        int id0 = q * 256;
        int b0 = ((id0 >> 3) * 64 + (id0 & 7)) * 32 + lane;
        #pragma unroll
        for (int g = 0; g < 8; ++g) br[g] = bp[b0 + g * 256];
    }

    #pragma unroll 1
    for (int u = 0; u < 256; ++u) {
        const int id    = q * 256 + u;
        const int idn   = id + 1;
        const int basen = (u < 255) ? ((idn >> 3) * 64 + (idn & 7)) * 32 + lane
                                    : ((id  >> 3) * 64 + (id  & 7)) * 32 + lane;

        float creg[8];
        #pragma unroll
        for (int z = 0; z < 8; ++z) creg[z] = 0.f;

        #pragma unroll
        for (int g = 0; g < 8; ++g) {
            const uint4 b = br[g];
            br[g] = bp[basen + g * 256];   // prefetch (u+1, g): distance 8 steps
            mma16816(creg + 0, areg + (2 * g) * 4,          b.x, b.y);
            mma16816(creg + 0, areg + (2 * g + 1) * 4,      b.z, b.w);
            mma16816(creg + 4, areg + 64 + (2 * g) * 4,     b.x, b.y);
            mma16816(creg + 4, areg + 64 + (2 * g + 1) * 4, b.z, b.w);
        }

        // epilogue per n8: subtract 0.5||e||^2 + running top-2 (4 slots)
        float2 c2 = __ldg(reinterpret_cast<const float2*>(g_c) + id * 4 + (lane & 3));
        int n0 = id * 8 + (lane & 3) * 2;
        float v;
        v = creg[0] - c2.x;
        if (v > bb[0]) { ss[0] = bb[0]; bb[0] = v; ii[0] = n0; } else if (v > ss[0]) ss[0] = v;
        v = creg[1] - c2.y;
        if (v > bb[0]) { ss[0] = bb[0]; bb[0] = v; ii[0] = n0 + 1; } else if (v > ss[0]) ss[0] = v;
        v = creg[2] - c2.x;
        if (v > bb[1]) { ss[1] = bb[1]; bb[1] = v; ii[1] = n0; } else if (v > ss[1]) ss[1] = v;
        v = creg[3] - c2.y;
        if (v > bb[1]) { ss[1] = bb[1]; bb[1] = v; ii[1] = n0 + 1; } else if (v > ss[1]) ss[1] = v;
        v = creg[4] - c2.x;
        if (v > bb[2]) { ss[2] = bb[2]; bb[2] = v; ii[2] = n0; } else if (v > ss[2]) ss[2] = v;
        v = creg[5] - c2.y;
        if (v > bb[2]) { ss[2] = bb[2]; bb[2] = v; ii[2] = n0 + 1; } else if (v > ss[2]) ss[2] = v;
        v = creg[6] - c2.x;
        if (v > bb[3]) { ss[3] = bb[3]; bb[3] = v; ii[3] = n0; } else if (v > ss[3]) ss[3] = v;
        v = creg[7] - c2.y;
        if (v > bb[3]) { ss[3] = bb[3]; bb[3] = v; ii[3] = n0 + 1; } else if (v > ss[3]) ss[3] = v;
    }

    // ================= reduction =================
    // quad merge within warp (lanes 0..3 of each quad hold different codes)
    #pragma unroll
    for (int sl = 0; sl < 4; ++sl) {
        float b2 = bb[sl], sec = ss[sl]; int i = ii[sl];
        #pragma unroll
        for (int off = 1; off <= 2; off <<= 1) {
            float ob = __shfl_xor_sync(0xffffffffu, b2, off);
            float os = __shfl_xor_sync(0xffffffffu, sec, off);
            int   oi = __shfl_xor_sync(0xffffffffu, i, off);
            if (ob > b2 || (ob == b2 && oi < i)) {
                sec = fmaxf(b2, os); b2 = ob; i = oi;
            } else {
                sec = fmaxf(sec, ob);
            }
        }
        if ((lane & 3) == 0) {
            int lrow = (sl >> 1) * 16 + (sl & 1) * 8 + (lane >> 2);
            sbv[wid][lrow] = b2;
            ssv[wid][lrow] = sec;
            sbi[wid][lrow] = i;
        }
    }
    __syncthreads();

    // merge 4 warps (disjoint code quarters) per row; write + flag
    if (tid < 32) {
        float va = sbv[0][tid], sa = ssv[0][tid];
        int   ia = sbi[0][tid];
        #pragma unroll
        for (int w = 1; w < 4; ++w) {
            float vb = sbv[w][tid], sb = ssv[w][tid];
            int   ib = sbi[w][tid];
            if (vb > va || (vb == va && ib < ia)) {
                sa = fmaxf(va, sb); va = vb; ia = ib;
            } else {
                sa = fmaxf(sa, vb);
            }
        }
        int row = row0 + tid;
        g_idx[row] = ia;
        if (va - sa < THRESH) {
            int sidx = atomicAdd(&g_nflag, 1);
            if (sidx < FLAG_CAP) { g_flag[sidx] = row; g_rkey[sidx] = 0ull; }
        }
    }
}

// ============================================================
// Exact fp32 rescue for narrow-margin rows.
// ============================================================
__device__ __forceinline__ unsigned long long score_key(float v, int j) {
    uint32_t u = __float_as_uint(v);
    u = (u & 0x80000000u) ? ~u : (u | 0x80000000u);
    return ((unsigned long long)u << 32) | (uint32_t)(0xFFFFFFFFu ^ (uint32_t)j);
}

__global__ void rescue_kernel(const float* __restrict__ input,
                              const float* __restrict__ embed) {
    __shared__ float xs[16][DIM];
    __shared__ unsigned long long wb[8][16];
    int nf = g_nflag; if (nf > FLAG_CAP) nf = FLAG_CAP;
    const int tid = threadIdx.x, wid = tid >> 5, lane = tid & 31;

    for (int base = blockIdx.y * 16; base < nf; base += 16 * 16) {
        int nrows = nf - base; if (nrows > 16) nrows = 16;
        __syncthreads();
        for (int i = tid; i < nrows * DIM; i += 256) {
            int r = i >> 8, d = i & 255;
            xs[r][d] = input[(size_t)g_flag[base + r] * DIM + d];
        }
        __syncthreads();

        int j0 = blockIdx.x * 1024 + tid;     // codes j0 + {0,256,512,768}
        float acc[4][16];
        #pragma unroll
        for (int qq = 0; qq < 4; ++qq)
            #pragma unroll
            for (int r = 0; r < 16; ++r) acc[qq][r] = 0.f;

        #pragma unroll 4
        for (int d = 0; d < DIM; ++d) {
            float e0 = embed[(size_t)d * NE + j0];
            float e1 = embed[(size_t)d * NE + j0 + 256];
            float e2 = embed[(size_t)d * NE + j0 + 512];
            float e3 = embed[(size_t)d * NE + j0 + 768];
            #pragma unroll
            for (int r = 0; r < 16; ++r) {
                float x = xs[r][d];
                acc[0][r] += e0 * x;
                acc[1][r] += e1 * x;
                acc[2][r] += e2 * x;
                acc[3][r] += e3 * x;
            }
        }
        float c0 = g_c[j0], c1 = g_c[j0 + 256], c2 = g_c[j0 + 512], c3 = g_c[j0 + 768];

        #pragma unroll 1
        for (int r = 0; r < 16; ++r) {
            float bv = acc[0][r] - c0; int bj = j0;
            float v1 = acc[1][r] - c1; if (v1 > bv) { bv = v1; bj = j0 + 256; }
            float v2 = acc[2][r] - c2; if (v2 > bv) { bv = v2; bj = j0 + 512; }
            float v3 = acc[3][r] - c3; if (v3 > bv) { bv = v3; bj = j0 + 768; }
            unsigned long long key = score_key(bv, bj);
            #pragma unroll
            for (int o = 16; o; o >>= 1) {
                unsigned long long other = __shfl_xor_sync(0xffffffffu, key, o);
                if (other > key) key = other;
            }
            if (lane == 0) wb[wid][r] = key;
        }
        __syncthreads();
        if (tid < nrows) {
            unsigned long long k = wb[0][tid];
            #pragma unroll
            for (int w = 1; w < 8; ++w) if (wb[w][tid] > k) k = wb[w][tid];
            atomicMax(&g_rkey[base + tid], k);
        }
    }
}

__global__ void extract_kernel() {
    int nf = g_nflag; if (nf > FLAG_CAP) nf = FLAG_CAP;
    for (int i = threadIdx.x; i < nf; i += 256) {
        unsigned long long k = g_rkey[i];
        g_idx[g_flag[i]] = (int)(0xFFFFFFFFu ^ (uint32_t)(k & 0xFFFFFFFFull));
    }
}

// ============================================================
// Output: gather, commitment loss, indices.
// ============================================================
__global__ void output_kernel(const float* __restrict__ input,
                              float* __restrict__ out, int write_extra) {
    int row  = blockIdx.x * 8 + (threadIdx.x >> 5);
    int lane = threadIdx.x & 31;
    int j = g_idx[row];
    const float4* x4 = reinterpret_cast<const float4*>(input + (size_t)row * DIM);
    const float4* e4 = reinterpret_cast<const float4*>(g_eT + (size_t)j * DIM);
    float4*       q4 = reinterpret_cast<float4*>(out + (size_t)row * DIM);
    float s = 0.f;
    #pragma unroll
    for (int t = 0; t < 2; ++t) {
        int d4 = lane + t * 32;
        float4 e = e4[d4];
        float4 x = x4[d4];
        q4[d4] = e;
        float a = e.x - x.x, b = e.y - x.y, c = e.z - x.z, d = e.w - x.w;
        s += a * a + b * b + c * c + d * d;
    }
    #pragma unroll
    for (int o = 16; o; o >>= 1) s += __shfl_xor_sync(0xffffffffu, s, o);
    if (lane == 0) {
        atomicAdd(&g_diff, (double)s);
        if (write_extra) out[(size_t)NROWS * DIM + 1 + row] = (float)j;
    }
}

__global__ void finalize_kernel(float* __restrict__ out, int write_extra) {
    if (write_extra)
        out[(size_t)NROWS * DIM] = (float)(g_diff * (1.0 / ((double)NROWS * (double)DIM)));
}

// ============================================================
extern "C" void kernel_launch(void* const* d_in, const int* in_sizes, int n_in,
                              void* d_out, int out_size) {
    const float* input = (const float*)d_in[0];
    const float* embed = (const float*)d_in[1];
    if (in_sizes[0] == NE * DIM && in_sizes[1] == NROWS * DIM) {
        input = (const float*)d_in[1];
        embed = (const float*)d_in[0];
    }
    float* out = (float*)d_out;
    int write_extra = (out_size >= NROWS * DIM + 1 + NROWS) ? 1 : 0;

    norms_part_kernel<<<dim3(NE / 256, 4), 256>>>(embed);
    norms_comb_kernel<<<NE / 256, 256>>>();
    transpose_kernel<<<dim3(NE / 32, DIM / 32), dim3(32, 8)>>>(embed);
    pack_kernel<<<DIM * NE / 256, 256>>>(embed);
    tc_argmin_kernel<<<NROWS / 32, 128>>>(input);
    rescue_kernel<<<dim3(8, 16), 256>>>(input, embed);
    extract_kernel<<<1, 256>>>();
    output_kernel<<<NROWS / 8, 256>>>(input, out, write_extra);
    finalize_kernel<<<1, 1>>>(out, write_extra);
}

// round 12
// speedup vs baseline: 1.6424x; 1.0913x over previous
#include <cuda_runtime.h>
#include <cuda_fp16.h>
#include <cstdint>

#define DIM    256
#define NE     8192
#define NROWS  32768
#define THRESH 0.04f
#define FLAG_CAP NROWS

// ---- device scratch ----
__device__ float  g_c[NE];                 // 0.5*||e_j||^2
__device__ float  g_cp[4][NE];             // norm partials (deterministic combine)
__device__ int    g_idx[NROWS];
__device__ float  g_eT[NE * DIM];          // fp32 transposed codebook (gather)
__device__ __half g_epk[NE * DIM];         // fp16 codebook, pre-packed MMA B-fragments
__device__ double g_diff;
__device__ int    g_nflag;
__device__ int    g_flag[FLAG_CAP];
__device__ unsigned long long g_rkey[FLAG_CAP];

__device__ __forceinline__ uint32_t smem_u32(const void* p) {
    uint32_t a;
    asm("{ .reg .u64 t; cvta.to.shared.u64 t, %1; cvt.u32.u64 %0, t; }" : "=r"(a) : "l"(p));
    return a;
}

__device__ __forceinline__ void ldmx4(uint32_t& r0, uint32_t& r1, uint32_t& r2, uint32_t& r3,
                                      uint32_t addr) {
    asm volatile("ldmatrix.sync.aligned.m8n8.x4.shared.b16 {%0,%1,%2,%3}, [%4];"
                 : "=r"(r0), "=r"(r1), "=r"(r2), "=r"(r3) : "r"(addr));
}

__device__ __forceinline__ void mma16816(float* c,
                                         const uint32_t* a,
                                         uint32_t b0, uint32_t b1) {
    asm volatile(
        "mma.sync.aligned.m16n8k16.row.col.f32.f16.f16.f32 "
        "{%0,%1,%2,%3}, {%4,%5,%6,%7}, {%8,%9}, {%0,%1,%2,%3};"
        : "+f"(c[0]), "+f"(c[1]), "+f"(c[2]), "+f"(c[3])
        : "r"(a[0]), "r"(a[1]), "r"(a[2]), "r"(a[3]), "r"(b0), "r"(b1));
}

// ============================================================
// Prep kernels
// ============================================================
__global__ void norms_part_kernel(const float* __restrict__ embed) {
    int j = blockIdx.x * 256 + threadIdx.x;
    int q = blockIdx.y;                    // dim quarter
    float s = 0.f;
    #pragma unroll 8
    for (int d = q * 64; d < q * 64 + 64; ++d) {
        float v = embed[(size_t)d * NE + j];
        s += v * v;
    }
    g_cp[q][j] = s;
}

__global__ void norms_comb_kernel() {
    int j = blockIdx.x * 256 + threadIdx.x;
    if (blockIdx.x == 0 && threadIdx.x == 0) { g_diff = 0.0; g_nflag = 0; }
    g_c[j] = 0.5f * (((g_cp[0][j] + g_cp[1][j]) + g_cp[2][j]) + g_cp[3][j]);
}

// Fused transpose (-> g_eT) + fp16 fragment pack (-> g_epk).
// Fragment unit (jt, ncol, g, p) = 512B: n8 x k32 (32 lanes x 16B).
// Lane l = nl*4 + ((kk>>1)&3), halves h = (kk>>3)*2 + (kk&1).
__global__ void transpose_pack_kernel(const float* __restrict__ embed) {
    __shared__ float t[32][33];
    int j0 = blockIdx.x * 32;
    int d0 = blockIdx.y * 32;
    int tx = threadIdx.x, ty = threadIdx.y;   // 32 x 8
    #pragma unroll
    for (int i = 0; i < 32; i += 8) {
        int d = d0 + ty + i;
        int j = j0 + tx;
        float v = embed[(size_t)d * NE + j];
        t[ty + i][tx] = v;
        // pack fragment element
        int jt = j >> 7;
        int ncol = (j >> 6) & 1;
        int p = (j >> 3) & 7;
        int nl = j & 7;
        int g = d >> 5;
        int kk = d & 31;
        int l = nl * 4 + ((kk >> 1) & 3);
        int h = ((kk >> 3) << 1) + (kk & 1);
        size_t unit = ((size_t)(jt * 2 + ncol) * 8 + g) * 8 + p;
        g_epk[unit * 256 + l * 8 + h] = __float2half(v);
    }
    __syncthreads();
    #pragma unroll
    for (int i = 0; i < 32; i += 8)
        g_eT[(size_t)(j0 + ty + i) * DIM + (d0 + tx)] = t[tx][ty + i];
}

// ============================================================
// Main HMMA kernel: 128 threads (4 warps), 32 rows/CTA, 1024 CTAs.
// Warp: m32 x distinct 2048-code quarter; B LDG-direct, distance-8 ring.
// 4 independent accumulator chains (k-chunk parity split) to break
// HMMA C-operand RAW stalls; merged with 8 FADD per u.
// ============================================================
__global__ void __launch_bounds__(128, 2)
tc_argmin_kernel(const float* __restrict__ input) {
    __shared__ __align__(16) __half stage[8192];  // 16KB: 32-row A staging
    __shared__ float sbv[4][32];
    __shared__ float ssv[4][32];
    __shared__ int   sbi[4][32];

    const int tid  = threadIdx.x;
    const int wid  = tid >> 5;    // warp = code quarter
    const int lane = tid & 31;
    const int row0 = blockIdx.x * 32;
    const int mat  = lane >> 3;
    const int rr   = lane & 7;

    // ================= prologue: A fragments (both m16 tiles) ==============
    uint32_t areg[128];   // 2 m-tiles x 16 k16-chunks x 4
    {
        const int r = tid & 31;     // row
        const int p = tid >> 5;     // segment 0..3 (64 halves each)
        const float4* src = reinterpret_cast<const float4*>(
            input + (size_t)(row0 + r) * DIM + p * 64);
        #pragma unroll
        for (int u = 0; u < 8; ++u) {
            float4 fa = src[u * 2 + 0];
            float4 fb = src[u * 2 + 1];
            __half2 h0 = __floats2half2_rn(fa.x, fa.y);
            __half2 h1 = __floats2half2_rn(fa.z, fa.w);
            __half2 h2 = __floats2half2_rn(fb.x, fb.y);
            __half2 h3 = __floats2half2_rn(fb.z, fb.w);
            uint4 pk;
            pk.x = *reinterpret_cast<uint32_t*>(&h0);
            pk.y = *reinterpret_cast<uint32_t*>(&h1);
            pk.z = *reinterpret_cast<uint32_t*>(&h2);
            pk.w = *reinterpret_cast<uint32_t*>(&h3);
            int g = p * 8 + u;
            int swg = (g & 24) | ((g ^ r) & 7);
            *reinterpret_cast<uint4*>(
                reinterpret_cast<char*>(stage) + r * 512 + swg * 16) = pk;
        }
        __syncthreads();
        #pragma unroll
        for (int mt = 0; mt < 2; ++mt) {
            const int m = mt * 16 + (mat & 1) * 8 + rr;
            #pragma unroll
            for (int c = 0; c < 16; ++c) {
                int g = c * 2 + (mat >> 1);
                int swg = (g & 24) | ((g ^ rr) & 7);
                uint32_t addr = smem_u32(stage) + (uint32_t)(m * 512 + swg * 16);
                ldmx4(areg[mt * 64 + c * 4 + 0], areg[mt * 64 + c * 4 + 1],
                      areg[mt * 64 + c * 4 + 2], areg[mt * 64 + c * 4 + 3], addr);
            }
        }
    }

    // ================= main loop: LDG-direct B, 4 accumulator chains =======
    const uint4* bp = reinterpret_cast<const uint4*>(g_epk);
    const int q = wid;

    float bb[4] = {-3.0e38f, -3.0e38f, -3.0e38f, -3.0e38f};
    float ss[4] = {-3.0e38f, -3.0e38f, -3.0e38f, -3.0e38f};
    int   ii[4] = {0, 0, 0, 0};

    uint4 br[8];   // slot g holds (u, g)
    {
        int id0 = q * 256;
        int b0 = ((id0 >> 3) * 64 + (id0 & 7)) * 32 + lane;
        #pragma unroll
        for (int g = 0; g < 8; ++g) br[g] = bp[b0 + g * 256];
    }

    #pragma unroll 1
    for (int u = 0; u < 256; ++u) {
        const int id    = q * 256 + u;
        const int idn   = id + 1;
        const int basen = (u < 255) ? ((idn >> 3) * 64 + (idn & 7)) * 32 + lane
                                    : ((id  >> 3) * 64 + (id  & 7)) * 32 + lane;

        // 4 chains: cA0=creg[0..3], cB0=creg[4..7], cA1=creg[8..11], cB1=creg[12..15]
        float creg[16];
        #pragma unroll
        for (int z = 0; z < 16; ++z) creg[z] = 0.f;

        #pragma unroll
        for (int g = 0; g < 8; ++g) {
            const uint4 b = br[g];
            br[g] = bp[basen + g * 256];   // prefetch (u+1, g)
            mma16816(creg + 0,  areg + (2 * g) * 4,          b.x, b.y);  // cA0
            mma16816(creg + 4,  areg + (2 * g + 1) * 4,      b.z, b.w);  // cB0
            mma16816(creg + 8,  areg + 64 + (2 * g) * 4,     b.x, b.y);  // cA1
            mma16816(creg + 12, areg + 64 + (2 * g + 1) * 4, b.z, b.w);  // cB1
        }

        // merge chains + subtract 0.5||e||^2 + running top-2 (4 slots)
        float2 c2 = __ldg(reinterpret_cast<const float2*>(g_c) + id * 4 + (lane & 3));
        int n0 = id * 8 + (lane & 3) * 2;
        float v;
        v = (creg[0] + creg[4]) - c2.x;
        if (v > bb[0]) { ss[0] = bb[0]; bb[0] = v; ii[0] = n0; } else if (v > ss[0]) ss[0] = v;
        v = (creg[1] + creg[5]) - c2.y;
        if (v > bb[0]) { ss[0] = bb[0]; bb[0] = v; ii[0] = n0 + 1; } else if (v > ss[0]) ss[0] = v;
        v = (creg[2] + creg[6]) - c2.x;
        if (v > bb[1]) { ss[1] = bb[1]; bb[1] = v; ii[1] = n0; } else if (v > ss[1]) ss[1] = v;
        v = (creg[3] + creg[7]) - c2.y;
        if (v > bb[1]) { ss[1] = bb[1]; bb[1] = v; ii[1] = n0 + 1; } else if (v > ss[1]) ss[1] = v;
        v = (creg[8] + creg[12]) - c2.x;
        if (v > bb[2]) { ss[2] = bb[2]; bb[2] = v; ii[2] = n0; } else if (v > ss[2]) ss[2] = v;
        v = (creg[9] + creg[13]) - c2.y;
        if (v > bb[2]) { ss[2] = bb[2]; bb[2] = v; ii[2] = n0 + 1; } else if (v > ss[2]) ss[2] = v;
        v = (creg[10] + creg[14]) - c2.x;
        if (v > bb[3]) { ss[3] = bb[3]; bb[3] = v; ii[3] = n0; } else if (v > ss[3]) ss[3] = v;
        v = (creg[11] + creg[15]) - c2.y;
        if (v > bb[3]) { ss[3] = bb[3]; bb[3] = v; ii[3] = n0 + 1; } else if (v > ss[3]) ss[3] = v;
    }

    // ================= reduction =================
    // quad merge within warp (lanes 0..3 of each quad hold different codes)
    #pragma unroll
    for (int sl = 0; sl < 4; ++sl) {
        float b2 = bb[sl], sec = ss[sl]; int i = ii[sl];
        #pragma unroll
        for (int off = 1; off <= 2; off <<= 1) {
            float ob = __shfl_xor_sync(0xffffffffu, b2, off);
            float os = __shfl_xor_sync(0xffffffffu, sec, off);
            int   oi = __shfl_xor_sync(0xffffffffu, i, off);
            if (ob > b2 || (ob == b2 && oi < i)) {
                sec = fmaxf(b2, os); b2 = ob; i = oi;
            } else {
                sec = fmaxf(sec, ob);
            }
        }
        if ((lane & 3) == 0) {
            int lrow = (sl >> 1) * 16 + (sl & 1) * 8 + (lane >> 2);
            sbv[wid][lrow] = b2;
            ssv[wid][lrow] = sec;
            sbi[wid][lrow] = i;
        }
    }
    __syncthreads();

    // merge 4 warps (disjoint code quarters) per row; write + flag
    if (tid < 32) {
        float va = sbv[0][tid], sa = ssv[0][tid];
        int   ia = sbi[0][tid];
        #pragma unroll
        for (int w = 1; w < 4; ++w) {
            float vb = sbv[w][tid], sb = ssv[w][tid];
            int   ib = sbi[w][tid];
            if (vb > va || (vb == va && ib < ia)) {
                sa = fmaxf(va, sb); va = vb; ia = ib;
            } else {
                sa = fmaxf(sa, vb);
            }
        }
        int row = row0 + tid;
        g_idx[row] = ia;
        if (va - sa < THRESH) {
            int sidx = atomicAdd(&g_nflag, 1);
            if (sidx < FLAG_CAP) { g_flag[sidx] = row; g_rkey[sidx] = 0ull; }
        }
    }
}

// ============================================================
// Exact fp32 rescue for narrow-margin rows.
// ============================================================
__device__ __forceinline__ unsigned long long score_key(float v, int j) {
    uint32_t u = __float_as_uint(v);
    u = (u & 0x80000000u) ? ~u : (u | 0x80000000u);
    return ((unsigned long long)u << 32) | (uint32_t)(0xFFFFFFFFu ^ (uint32_t)j);
}

__global__ void rescue_kernel(const float* __restrict__ input,
                              const float* __restrict__ embed) {
    __shared__ float xs[16][DIM];
    __shared__ unsigned long long wb[8][16];
    int nf = g_nflag; if (nf > FLAG_CAP) nf = FLAG_CAP;
    const int tid = threadIdx.x, wid = tid >> 5, lane = tid & 31;

    for (int base = blockIdx.y * 16; base < nf; base += 16 * 16) {
        int nrows = nf - base; if (nrows > 16) nrows = 16;
        __syncthreads();
        for (int i = tid; i < nrows * DIM; i += 256) {
            int r = i >> 8, d = i & 255;
            xs[r][d] = input[(size_t)g_flag[base + r] * DIM + d];
        }
        __syncthreads();

        int j0 = blockIdx.x * 1024 + tid;     // codes j0 + {0,256,512,768}
        float acc[4][16];
        #pragma unroll
        for (int qq = 0; qq < 4; ++qq)
            #pragma unroll
            for (int r = 0; r < 16; ++r) acc[qq][r] = 0.f;

        #pragma unroll 4
        for (int d = 0; d < DIM; ++d) {
            float e0 = embed[(size_t)d * NE + j0];
            float e1 = embed[(size_t)d * NE + j0 + 256];
            float e2 = embed[(size_t)d * NE + j0 + 512];
            float e3 = embed[(size_t)d * NE + j0 + 768];
            #pragma unroll
            for (int r = 0; r < 16; ++r) {
                float x = xs[r][d];
                acc[0][r] += e0 * x;
                acc[1][r] += e1 * x;
                acc[2][r] += e2 * x;
                acc[3][r] += e3 * x;
            }
        }
        float c0 = g_c[j0], c1 = g_c[j0 + 256], c2 = g_c[j0 + 512], c3 = g_c[j0 + 768];

        #pragma unroll 1
        for (int r = 0; r < 16; ++r) {
            float bv = acc[0][r] - c0; int bj = j0;
            float v1 = acc[1][r] - c1; if (v1 > bv) { bv = v1; bj = j0 + 256; }
            float v2 = acc[2][r] - c2; if (v2 > bv) { bv = v2; bj = j0 + 512; }
            float v3 = acc[3][r] - c3; if (v3 > bv) { bv = v3; bj = j0 + 768; }
            unsigned long long key = score_key(bv, bj);
            #pragma unroll
            for (int o = 16; o; o >>= 1) {
                unsigned long long other = __shfl_xor_sync(0xffffffffu, key, o);
                if (other > key) key = other;
            }
            if (lane == 0) wb[wid][r] = key;
        }
        __syncthreads();
        if (tid < nrows) {
            unsigned long long k = wb[0][tid];
            #pragma unroll
            for (int w = 1; w < 8; ++w) if (wb[w][tid] > k) k = wb[w][tid];
            atomicMax(&g_rkey[base + tid], k);
        }
    }
}

__global__ void extract_kernel() {
    int nf = g_nflag; if (nf > FLAG_CAP) nf = FLAG_CAP;
    for (int i = threadIdx.x; i < nf; i += 256) {
        unsigned long long k = g_rkey[i];
        g_idx[g_flag[i]] = (int)(0xFFFFFFFFu ^ (uint32_t)(k & 0xFFFFFFFFull));
    }
}

// ============================================================
// Output: gather, commitment loss, indices.
// ============================================================
__global__ void output_kernel(const float* __restrict__ input,
                              float* __restrict__ out, int write_extra) {
    int row  = blockIdx.x * 8 + (threadIdx.x >> 5);
    int lane = threadIdx.x & 31;
    int j = g_idx[row];
    const float4* x4 = reinterpret_cast<const float4*>(input + (size_t)row * DIM);
    const float4* e4 = reinterpret_cast<const float4*>(g_eT + (size_t)j * DIM);
    float4*       q4 = reinterpret_cast<float4*>(out + (size_t)row * DIM);
    float s = 0.f;
    #pragma unroll
    for (int t = 0; t < 2; ++t) {
        int d4 = lane + t * 32;
        float4 e = e4[d4];
        float4 x = x4[d4];
        q4[d4] = e;
        float a = e.x - x.x, b = e.y - x.y, c = e.z - x.z, d = e.w - x.w;
        s += a * a + b * b + c * c + d * d;
    }
    #pragma unroll
    for (int o = 16; o; o >>= 1) s += __shfl_xor_sync(0xffffffffu, s, o);
    if (lane == 0) {
        atomicAdd(&g_diff, (double)s);
        if (write_extra) out[(size_t)NROWS * DIM + 1 + row] = (float)j;
    }
}

__global__ void finalize_kernel(float* __restrict__ out, int write_extra) {
    if (write_extra)
        out[(size_t)NROWS * DIM] = (float)(g_diff * (1.0 / ((double)NROWS * (double)DIM)));
}

// ============================================================
extern "C" void kernel_launch(void* const* d_in, const int* in_sizes, int n_in,
                              void* d_out, int out_size) {
    const float* input = (const float*)d_in[0];
    const float* embed = (const float*)d_in[1];
    if (in_sizes[0] == NE * DIM && in_sizes[1] == NROWS * DIM) {
        input = (const float*)d_in[1];
        embed = (const float*)d_in[0];
    }
    float* out = (float*)d_out;
    int write_extra = (out_size >= NROWS * DIM + 1 + NROWS) ? 1 : 0;

    norms_part_kernel<<<dim3(NE / 256, 4), 256>>>(embed);
    norms_comb_kernel<<<NE / 256, 256>>>();
    transpose_pack_kernel<<<dim3(NE / 32, DIM / 32), dim3(32, 8)>>>(embed);
    tc_argmin_kernel<<<NROWS / 32, 128>>>(input);
    rescue_kernel<<<dim3(8, 16), 256>>>(input, embed);
    extract_kernel<<<1, 256>>>();
    output_kernel<<<NROWS / 8, 256>>>(input, out, write_extra);
    finalize_kernel<<<1, 1>>>(out, write_extra);
}